// round 8
// baseline (speedup 1.0000x reference)
#include <cuda_runtime.h>
#include <cuda_bf16.h>
#include <math.h>
#include <stdint.h>

#define BQ    1024
#define NM    50000
#define DD    256
#define MAXA  200
#define KSEL  8
#define KS2   16               // survivors per split (pruning stage)
#define NSPLIT 37
#define SPLEN  1352            // ceil(50000/37)
#define NC2   (NSPLIT*KS2)     // 592 approx candidates per query
#define RCAP  64               // refine-list capacity
#define MARGIN 4.0f            // > 2 * worst-case approx arg error (~1.5)
#define BIGF  3.0e38f

// -------- device scratch --------
__device__ unsigned g_mem_hi[NM * 128];   // bf16x2: col pair per u32
__device__ unsigned g_mem_lo[NM * 128];
__device__ unsigned g_q_hi[BQ * 128];
__device__ unsigned g_q_lo[BQ * 128];
__device__ float    g_mem_sq[NM];
__device__ float    g_q_sq[BQ];
__device__ float    g_cand_arg[BQ * NC2];
__device__ int      g_cand_idx[BQ * NC2];

// ===================== PTX helpers =====================
__device__ __forceinline__ uint32_t smem_u32(const void* p) {
    uint32_t a;
    asm("{ .reg .u64 t; cvta.to.shared.u64 t, %1; cvt.u32.u64 %0, t; }" : "=r"(a) : "l"(p));
    return a;
}
#define LDSM_X4(r0, r1, r2, r3, addr) \
    asm volatile("ldmatrix.sync.aligned.m8n8.x4.shared.b16 {%0,%1,%2,%3}, [%4];" \
        : "=r"(r0), "=r"(r1), "=r"(r2), "=r"(r3) : "r"(addr))

__device__ __forceinline__ void mma_bf16(float* c, const uint32_t* a,
                                         uint32_t b0, uint32_t b1) {
    asm volatile("mma.sync.aligned.m16n8k16.row.col.f32.bf16.bf16.f32 "
        "{%0,%1,%2,%3},{%4,%5,%6,%7},{%8,%9},{%0,%1,%2,%3};"
        : "+f"(c[0]), "+f"(c[1]), "+f"(c[2]), "+f"(c[3])
        : "r"(a[0]), "r"(a[1]), "r"(a[2]), "r"(a[3]), "r"(b0), "r"(b1));
}

// bf16x2 unpack: even dim in low 16 bits, odd dim in high 16 bits
__device__ __forceinline__ float bflo(uint32_t v) { return __uint_as_float(v << 16); }
__device__ __forceinline__ float bfhi(uint32_t v) { return __uint_as_float(v & 0xffff0000u); }

// -------- packed f32x2 helpers (transform kernel) --------
__device__ __forceinline__ unsigned long long dup2(float x) {
    unsigned long long r;
    asm("mov.b64 %0, {%1, %1};" : "=l"(r) : "f"(x));
    return r;
}
__device__ __forceinline__ void ffma2(unsigned long long& d,
                                      unsigned long long a, unsigned long long b) {
    asm("fma.rn.f32x2 %0, %1, %2, %0;" : "+l"(d) : "l"(a), "l"(b));
}
__device__ __forceinline__ float2 unpack2(unsigned long long v) {
    float2 r;
    asm("mov.b64 {%0, %1}, %2;" : "=f"(r.x), "=f"(r.y) : "l"(v));
    return r;
}

// ============================================================
// Kernel 1: H = tanh(X@W+b), Poincare rescale, |h|^2, bf16 hi/lo split out.
// ============================================================
__global__ __launch_bounds__(256, 2)
void transform_kernel(const float* __restrict__ X, const float* __restrict__ W,
                      const float* __restrict__ bias,
                      unsigned* __restrict__ Hhi, unsigned* __restrict__ Hlo,
                      float* __restrict__ SQ, int M)
{
    __shared__ float  Xs[64][17];
    __shared__ float2 Ws2[16][128];
    __shared__ float  s_scale[64];

    const int tid = threadIdx.x;
    const int tx = tid & 15, ty = tid >> 4;
    const int row0 = blockIdx.x * 64;

    unsigned long long acc2[4][8];
#pragma unroll
    for (int i = 0; i < 4; i++)
#pragma unroll
        for (int j = 0; j < 8; j++) acc2[i][j] = 0ull;

    for (int kc = 0; kc < DD; kc += 16) {
#pragma unroll
        for (int e = tid; e < 64 * 16; e += 256) {
            int r = e >> 4, k = e & 15;
            float v = 0.f;
            if (row0 + r < M) v = X[(row0 + r) * DD + kc + k];
            Xs[r][k] = v;
        }
#pragma unroll
        for (int e = tid; e < 16 * 256; e += 256) {
            int k = e >> 8, c = e & 255;
            ((float*)Ws2)[k * 256 + c] = W[(kc + k) * DD + c];
        }
        __syncthreads();
#pragma unroll
        for (int k = 0; k < 16; k++) {
            unsigned long long a2[4], b2[8];
#pragma unroll
            for (int i = 0; i < 4; i++) a2[i] = dup2(Xs[ty + 16 * i][k]);
#pragma unroll
            for (int j = 0; j < 8; j++) {
                float2 bv = Ws2[k][tx + 16 * j];
                b2[j] = *(unsigned long long*)&bv;
            }
#pragma unroll
            for (int i = 0; i < 4; i++)
#pragma unroll
                for (int j = 0; j < 8; j++)
                    ffma2(acc2[i][j], a2[i], b2[j]);
        }
        __syncthreads();
    }

    const float2* bias2 = (const float2*)bias;
    float2 hv[4][8];
    float psum[4];
#pragma unroll
    for (int i = 0; i < 4; i++) {
        psum[i] = 0.f;
#pragma unroll
        for (int j = 0; j < 8; j++) {
            float2 bb = bias2[tx + 16 * j];
            float2 v = unpack2(acc2[i][j]);
            v.x = tanhf(v.x + bb.x);
            v.y = tanhf(v.y + bb.y);
            hv[i][j] = v;
            psum[i] += v.x * v.x + v.y * v.y;
        }
    }
#pragma unroll
    for (int off = 1; off < 16; off <<= 1) {
#pragma unroll
        for (int i = 0; i < 4; i++)
            psum[i] += __shfl_xor_sync(0xffffffffu, psum[i], off);
    }
    if (tx == 0) {
#pragma unroll
        for (int i = 0; i < 4; i++) {
            int r = ty + 16 * i;
            float norm = sqrtf(psum[i]);
            float sc = (norm > 0.95f) ? 0.95f / norm : 1.0f;
            s_scale[r] = sc;
            if (row0 + r < M) SQ[row0 + r] = psum[i] * sc * sc;
        }
    }
    __syncthreads();
#pragma unroll
    for (int i = 0; i < 4; i++) {
        int r = ty + 16 * i;
        if (row0 + r >= M) continue;
        float sc = s_scale[r];
#pragma unroll
        for (int j = 0; j < 8; j++) {
            float2 v = hv[i][j];
            v.x *= sc; v.y *= sc;
            __nv_bfloat16 hx = __float2bfloat16(v.x);
            __nv_bfloat16 hy = __float2bfloat16(v.y);
            __nv_bfloat16 lx = __float2bfloat16(v.x - __bfloat162float(hx));
            __nv_bfloat16 ly = __float2bfloat16(v.y - __bfloat162float(hy));
            size_t o = (size_t)(row0 + r) * 128 + tx + 16 * j;
            Hhi[o] = ((unsigned)__bfloat16_as_ushort(hy) << 16) | __bfloat16_as_ushort(hx);
            Hlo[o] = ((unsigned)__bfloat16_as_ushort(ly) << 16) | __bfloat16_as_ushort(lx);
        }
    }
}

// ============================================================
// Kernel 2: bf16 hi-only mma GEMM (pruning pass) + approx arg + top-16/split.
// CTA 128q x 64m, 8 warps, BK=64. One mma term: hi*hi.
// ============================================================
#define RS       144
#define QTILE_B  (128 * RS)                  // 18432
#define MTILE_B  (64 * RS)                   // 9216
#define OFF_QH   0
#define OFF_MH   (QTILE_B)                   // 18432
#define ARGBUF_B (128 * 72 * 4)              // 36864 (overlays tiles + pad)
#define OFF_YS   (ARGBUF_B)                  // 36864
#define OFF_TA   (OFF_YS + 256)              // 37120
#define OFF_TI   (OFF_TA + 128 * KS2 * 4)    // 45312
#define DSMEM_SZ (OFF_TI + 128 * KS2 * 4)    // 53504
#define ABROW    72

__device__ __forceinline__ void fill_q(char* dst, const uint4* src,
                                       int q0, int kc8, int tid) {
#pragma unroll
    for (int it = 0; it < 4; it++) {
        int idx = tid + 256 * it;
        int r = idx >> 3, kb = idx & 7;
        uint4 v = src[(size_t)(q0 + r) * 32 + kc8 + kb];
        *(uint4*)(dst + r * RS + kb * 16) = v;
    }
}
__device__ __forceinline__ void fill_m(char* dst, const uint4* src,
                                       int m0, int kc8, int mend, int tid) {
#pragma unroll
    for (int it = 0; it < 2; it++) {
        int idx = tid + 256 * it;
        int r = idx >> 3, kb = idx & 7;
        uint4 v = make_uint4(0u, 0u, 0u, 0u);
        if (m0 + r < mend) v = src[(size_t)(m0 + r) * 32 + kc8 + kb];
        *(uint4*)(dst + r * RS + kb * 16) = v;
    }
}

__device__ __forceinline__ void topk_insert(float* ta, int* ti, float a, int m,
                                            float& worst) {
    float mv = -1.f; int mp = 0;
#pragma unroll
    for (int s = 0; s < KS2; s++) {
        float v = ta[s];
        if (v > mv) { mv = v; mp = s; }
    }
    ta[mp] = a; ti[mp] = m;
    mv = -1.f;
#pragma unroll
    for (int s = 0; s < KS2; s++) {
        float v = ta[s];
        if (v > mv) mv = v;
    }
    worst = mv;
}

__global__ __launch_bounds__(256, 2)
void dist_topk_kernel()
{
    extern __shared__ char sb[];
    const uint32_t sbase = smem_u32(sb);

    float* tYS = (float*)(sb + OFF_YS);
    float* ta_all = (float*)(sb + OFF_TA);
    int*   ti_all = (int*)(sb + OFF_TI);
    float* argbuf = (float*)(sb + OFF_QH);

    const int tid = threadIdx.x;
    const int lane = tid & 31;
    const int wid = tid >> 5;
    const int warp_q = wid & 3;
    const int warp_m = wid >> 2;
    const int g4 = lane >> 2;
    const int tg = lane & 3;

    const int q0 = blockIdx.x * 128;
    const int mstart = blockIdx.y * SPLEN;
    const int mend = min(mstart + SPLEN, NM);

    const uint32_t aOff = (uint32_t)((warp_q * 32 + (lane & 7) + ((lane >> 3) & 1) * 8) * RS
                                     + (((lane >> 4) & 1) * 8) * 2);
    const uint32_t bOff = (uint32_t)((warp_m * 32 + (lane & 7) + ((lane >> 4) & 1) * 8) * RS
                                     + (((lane >> 3) & 1) * 8) * 2);
    const uint32_t u_qh = sbase + OFF_QH;
    const uint32_t u_mh = sbase + OFF_MH;

    float xs[2][2], inv1x[2][2];
#pragma unroll
    for (int i = 0; i < 2; i++)
#pragma unroll
        for (int r = 0; r < 2; r++) {
            float v = g_q_sq[q0 + warp_q * 32 + i * 16 + r * 8 + g4];
            xs[i][r] = v;
            inv1x[i][r] = 1.0f - v;
        }

    if (tid < 128) {
        float* ta = ta_all + tid * KS2;
        int* ti = ti_all + tid * KS2;
#pragma unroll
        for (int s = 0; s < KS2; s++) { ta[s] = BIGF; ti[s] = 0x7fffffff; }
    }
    float worst = BIGF;
    __syncthreads();

    const uint4* pQH = (const uint4*)g_q_hi;
    const uint4* pMH = (const uint4*)g_mem_hi;

    for (int m0 = mstart; m0 < mend; m0 += 64) {
        if (tid < 64) tYS[tid] = (m0 + tid < mend) ? g_mem_sq[m0 + tid] : 0.f;

        float acc[2][4][4];
#pragma unroll
        for (int i = 0; i < 2; i++)
#pragma unroll
            for (int j = 0; j < 4; j++)
#pragma unroll
                for (int c = 0; c < 4; c++) acc[i][j][c] = 0.f;

        for (int kc8 = 0; kc8 < 32; kc8 += 8) {
            fill_q(sb + OFF_QH, pQH, q0, kc8, tid);
            fill_m(sb + OFF_MH, pMH, m0, kc8, mend, tid);
            __syncthreads();

#pragma unroll
            for (int ks = 0; ks < 4; ks++) {
                uint32_t ah[2][4], bh[2][4];
                const uint32_t aA = u_qh + aOff + ks * 32;
#pragma unroll
                for (int i = 0; i < 2; i++)
                    LDSM_X4(ah[i][0], ah[i][1], ah[i][2], ah[i][3], aA + i * (16 * RS));
                const uint32_t bA = u_mh + bOff + ks * 32;
#pragma unroll
                for (int jj = 0; jj < 2; jj++)
                    LDSM_X4(bh[jj][0], bh[jj][1], bh[jj][2], bh[jj][3],
                            bA + jj * (16 * RS));
#pragma unroll
                for (int i = 0; i < 2; i++)
#pragma unroll
                    for (int j = 0; j < 4; j++) {
                        int jj = j >> 1, s = (j & 1) * 2;
                        mma_bf16(acc[i][j], ah[i], bh[jj][s], bh[jj][s + 1]);
                    }
            }
            __syncthreads();
        }

        // epilogue: approx args -> argbuf
#pragma unroll
        for (int i = 0; i < 2; i++)
#pragma unroll
            for (int r = 0; r < 2; r++) {
                int q = warp_q * 32 + i * 16 + r * 8 + g4;
                float xsi = xs[i][r], inv = inv1x[i][r];
#pragma unroll
                for (int j = 0; j < 4; j++) {
                    int ml = warp_m * 32 + j * 8 + 2 * tg;
                    float dA = acc[i][j][r * 2 + 0];
                    float dB = acc[i][j][r * 2 + 1];
                    float yA = tYS[ml], yB = tYS[ml + 1];
                    float d2A = fmaxf(xsi + yA - 2.f * dA, 0.f);
                    float d2B = fmaxf(xsi + yB - 2.f * dB, 0.f);
                    float argA = 1.f + 2.f * d2A / (inv * (1.f - yA) + 1e-8f);
                    float argB = 1.f + 2.f * d2B / (inv * (1.f - yB) + 1e-8f);
                    bool vA = (m0 + ml < mend), vB = (m0 + ml + 1 < mend);
                    float2 w = make_float2(vA ? argA : BIGF, vB ? argB : BIGF);
                    *(float2*)&argbuf[q * ABROW + ml] = w;
                }
            }
        __syncthreads();

        if (tid < 128) {
            int q = tid;
            float* ta = ta_all + q * KS2;
            int* ti = ti_all + q * KS2;
#pragma unroll
            for (int c4 = 0; c4 < 16; c4++) {
                float4 v = *(const float4*)&argbuf[q * ABROW + c4 * 4];
                float av[4] = {v.x, v.y, v.z, v.w};
#pragma unroll
                for (int e = 0; e < 4; e++) {
                    float a = av[e];
                    if (a < worst)
                        topk_insert(ta, ti, a, m0 + c4 * 4 + e, worst);
                }
            }
        }
        __syncthreads();
    }

    if (tid < 128) {
        int base = ((q0 + tid) * NSPLIT + blockIdx.y) * KS2;
        float* ta = ta_all + tid * KS2;
        int* ti = ti_all + tid * KS2;
#pragma unroll
        for (int s = 0; s < KS2; s++) {
            g_cand_arg[base + s] = ta[s];
            g_cand_idx[base + s] = ti[s];
        }
    }
}

// ============================================================
// Kernel 3: approx top-8 -> threshold prune -> EXACT fp32 rerank -> softmax.
// ============================================================
__global__ void merge_kernel(const float* __restrict__ masks, float* __restrict__ out)
{
    __shared__ float ca[NC2];
    __shared__ int   ci[NC2];
    __shared__ float qf[DD];
    __shared__ int   ridx[RCAP];
    __shared__ float ra[RCAP];
    __shared__ float wa[8];
    __shared__ int   wi[8], wp[8];
    __shared__ float sel_a[KSEL];
    __shared__ int   sel_i[KSEL];
    __shared__ int   rpos[KSEL];
    __shared__ float rval[KSEL];
    __shared__ int   scnt;

    const int q = blockIdx.x;
    const int tid = threadIdx.x;
    const int lane = tid & 31, wid = tid >> 5;

    if (tid == 0) scnt = 0;
    for (int c = tid; c < NC2; c += 256) {
        ca[c] = fmaxf(g_cand_arg[q * NC2 + c], 1.0f + 1e-6f);
        ci[c] = g_cand_idx[q * NC2 + c];
    }
    // reconstruct query vector fp32 = hi + lo
    if (tid < 128) {
        unsigned h = g_q_hi[q * 128 + tid];
        unsigned l = g_q_lo[q * 128 + tid];
        qf[2 * tid + 0] = bflo(h) + bflo(l);
        qf[2 * tid + 1] = bfhi(h) + bfhi(l);
    }
    __syncthreads();

    // ---- approx top-8 (for threshold) ----
    for (int r = 0; r < KSEL; r++) {
        float ba = BIGF; int bi = 0x7fffffff, bp = 0;
        for (int c = tid; c < NC2; c += 256) {
            float a = ca[c]; int i = ci[c];
            if (a < ba || (a == ba && i < bi)) { ba = a; bi = i; bp = c; }
        }
#pragma unroll
        for (int off = 16; off; off >>= 1) {
            float oa = __shfl_down_sync(0xffffffffu, ba, off);
            int oi = __shfl_down_sync(0xffffffffu, bi, off);
            int op = __shfl_down_sync(0xffffffffu, bp, off);
            if (oa < ba || (oa == ba && oi < bi)) { ba = oa; bi = oi; bp = op; }
        }
        if (lane == 0) { wa[wid] = ba; wi[wid] = bi; wp[wid] = bp; }
        __syncthreads();
        if (tid == 0) {
            float fa = wa[0]; int fi = wi[0], fp = wp[0];
#pragma unroll
            for (int w = 1; w < 8; w++) {
                if (wa[w] < fa || (wa[w] == fa && wi[w] < fi)) {
                    fa = wa[w]; fi = wi[w]; fp = wp[w];
                }
            }
            sel_a[r] = fa; rpos[r] = fp; rval[r] = fa;
            ca[fp] = BIGF;
        }
        __syncthreads();
    }
    // restore removed entries so the threshold scan sees original values
    if (tid < KSEL) ca[rpos[tid]] = rval[tid];
    __syncthreads();

    // ---- build refine list: everything within MARGIN of approx 8th ----
    const float thresh = sel_a[KSEL - 1] + MARGIN;
    for (int c = tid; c < NC2; c += 256) {
        if (ca[c] <= thresh) {
            int p = atomicAdd(&scnt, 1);
            if (p < RCAP) ridx[p] = ci[c];
        }
    }
    __syncthreads();
    const int cnt = min(scnt, RCAP);
    const float x_sq = g_q_sq[q];
    const float invx = 1.0f - x_sq;

    // ---- exact fp32 dots for refine candidates (warp per candidate) ----
    for (int c = wid; c < cnt; c += 8) {
        int m = ridx[c];
        const uint4* ph = (const uint4*)(g_mem_hi + (size_t)m * 128);
        const uint4* pl = (const uint4*)(g_mem_lo + (size_t)m * 128);
        uint4 h = ph[lane], l = pl[lane];
        const float* qp = &qf[lane * 8];
        float dot;
        dot  = (bflo(h.x) + bflo(l.x)) * qp[0];
        dot += (bfhi(h.x) + bfhi(l.x)) * qp[1];
        dot += (bflo(h.y) + bflo(l.y)) * qp[2];
        dot += (bfhi(h.y) + bfhi(l.y)) * qp[3];
        dot += (bflo(h.z) + bflo(l.z)) * qp[4];
        dot += (bfhi(h.z) + bfhi(l.z)) * qp[5];
        dot += (bflo(h.w) + bflo(l.w)) * qp[6];
        dot += (bfhi(h.w) + bfhi(l.w)) * qp[7];
#pragma unroll
        for (int off = 16; off; off >>= 1)
            dot += __shfl_xor_sync(0xffffffffu, dot, off);
        if (lane == 0) {
            float ysq = g_mem_sq[m];
            float d2 = fmaxf(x_sq + ysq - 2.f * dot, 0.f);
            float arg = 1.f + 2.f * d2 / (invx * (1.f - ysq) + 1e-8f);
            ra[c] = fmaxf(arg, 1.0f + 1e-6f);
        }
    }
    __syncthreads();

    // ---- final exact top-8 (warp 0) ----
    if (wid == 0) {
        for (int r = 0; r < KSEL; r++) {
            float ba = BIGF; int bi = 0x7fffffff, bp = 0;
            for (int c = lane; c < cnt; c += 32) {
                float a = ra[c]; int i = ridx[c];
                if (a < ba || (a == ba && i < bi)) { ba = a; bi = i; bp = c; }
            }
#pragma unroll
            for (int off = 16; off; off >>= 1) {
                float oa = __shfl_down_sync(0xffffffffu, ba, off);
                int oi = __shfl_down_sync(0xffffffffu, bi, off);
                int op = __shfl_down_sync(0xffffffffu, bp, off);
                if (oa < ba || (oa == ba && oi < bi)) { ba = oa; bi = oi; bp = op; }
            }
            ba = __shfl_sync(0xffffffffu, ba, 0);
            bi = __shfl_sync(0xffffffffu, bi, 0);
            bp = __shfl_sync(0xffffffffu, bp, 0);
            if (lane == 0) {
                sel_a[r] = ba; sel_i[r] = bi;
                ra[bp] = BIGF;
            }
            __syncwarp();
        }
    }
    __syncthreads();

    if (tid == 0) {
        float d[KSEL];
#pragma unroll
        for (int s = 0; s < KSEL; s++) d[s] = acoshf(sel_a[s]);
        float d0 = d[0];
        float e[KSEL], sum = 0.f;
#pragma unroll
        for (int s = 0; s < KSEL; s++) { e[s] = expf(d0 - d[s]); sum += e[s]; }
        float inv = 1.0f / sum;
#pragma unroll
        for (int s = 0; s < KSEL; s++) out[q * KSEL + s] = e[s] * inv;
    }
    __syncthreads();

    float4* hout = (float4*)(out + (size_t)BQ * KSEL);
    for (int e = tid; e < KSEL * (MAXA / 4); e += 256) {
        int s = e / (MAXA / 4), a4 = e - s * (MAXA / 4);
        const float4* src = (const float4*)(masks + (size_t)sel_i[s] * MAXA);
        hout[((size_t)q * KSEL + s) * (MAXA / 4) + a4] = src[a4];
    }
}

// ============================================================
extern "C" void kernel_launch(void* const* d_in, const int* in_sizes, int n_in,
                              void* d_out, int out_size)
{
    (void)in_sizes; (void)n_in; (void)out_size;
    const float* q_emb  = (const float*)d_in[0];
    const float* m_emb  = (const float*)d_in[1];
    const float* masks  = (const float*)d_in[2];
    const float* W      = (const float*)d_in[3];
    const float* bias   = (const float*)d_in[4];
    float* out = (float*)d_out;

    unsigned *d_mhi, *d_mlo, *d_qhi, *d_qlo;
    float *d_msq, *d_qsq;
    cudaGetSymbolAddress((void**)&d_mhi, g_mem_hi);
    cudaGetSymbolAddress((void**)&d_mlo, g_mem_lo);
    cudaGetSymbolAddress((void**)&d_qhi, g_q_hi);
    cudaGetSymbolAddress((void**)&d_qlo, g_q_lo);
    cudaGetSymbolAddress((void**)&d_msq, g_mem_sq);
    cudaGetSymbolAddress((void**)&d_qsq, g_q_sq);

    cudaFuncSetAttribute(dist_topk_kernel,
                         cudaFuncAttributeMaxDynamicSharedMemorySize, DSMEM_SZ);

    transform_kernel<<<(NM + 63) / 64, 256>>>(m_emb, W, bias, d_mhi, d_mlo, d_msq, NM);
    transform_kernel<<<(BQ + 63) / 64, 256>>>(q_emb, W, bias, d_qhi, d_qlo, d_qsq, BQ);

    dim3 g2(BQ / 128, NSPLIT);
    dist_topk_kernel<<<g2, 256, DSMEM_SZ>>>();

    merge_kernel<<<BQ, 256>>>(masks, out);
}

// round 10
// speedup vs baseline: 1.3805x; 1.3805x over previous
#include <cuda_runtime.h>
#include <cuda_bf16.h>
#include <math.h>
#include <stdint.h>

#define BQ    1024
#define NM    50000
#define DD    256
#define MAXA  200
#define KSEL  8
#define NSPLIT 37
#define SPLEN  1352            // ceil(50000/37)
#define CPS   32               // candidates per (query, split): 8 threads x top-4
#define NC2   (NSPLIT*CPS)     // 1184 candidates per query at merge
#define RCAP  64               // refine-list capacity
#define MARGIN 4.0f            // > 2 * worst-case hi-only arg error (~1.5)
#define BIGF  3.0e38f

// -------- device scratch --------
__device__ unsigned g_mem_hi[NM * 128];   // bf16x2: col pair per u32
__device__ unsigned g_mem_lo[NM * 128];
__device__ unsigned g_q_hi[BQ * 128];
__device__ unsigned g_q_lo[BQ * 128];
__device__ float    g_mem_sq[NM];
__device__ float    g_q_sq[BQ];
__device__ float    g_cand_arg[BQ * NC2];
__device__ int      g_cand_idx[BQ * NC2];

// ===================== PTX helpers =====================
__device__ __forceinline__ uint32_t smem_u32(const void* p) {
    uint32_t a;
    asm("{ .reg .u64 t; cvta.to.shared.u64 t, %1; cvt.u32.u64 %0, t; }" : "=r"(a) : "l"(p));
    return a;
}
#define LDSM_X4(r0, r1, r2, r3, addr) \
    asm volatile("ldmatrix.sync.aligned.m8n8.x4.shared.b16 {%0,%1,%2,%3}, [%4];" \
        : "=r"(r0), "=r"(r1), "=r"(r2), "=r"(r3) : "r"(addr))

__device__ __forceinline__ void mma_bf16(float* c, const uint32_t* a,
                                         uint32_t b0, uint32_t b1) {
    asm volatile("mma.sync.aligned.m16n8k16.row.col.f32.bf16.bf16.f32 "
        "{%0,%1,%2,%3},{%4,%5,%6,%7},{%8,%9},{%0,%1,%2,%3};"
        : "+f"(c[0]), "+f"(c[1]), "+f"(c[2]), "+f"(c[3])
        : "r"(a[0]), "r"(a[1]), "r"(a[2]), "r"(a[3]), "r"(b0), "r"(b1));
}

// bf16x2 unpack: even dim in low 16 bits, odd dim in high 16 bits
__device__ __forceinline__ float bflo(uint32_t v) { return __uint_as_float(v << 16); }
__device__ __forceinline__ float bfhi(uint32_t v) { return __uint_as_float(v & 0xffff0000u); }

// -------- packed f32x2 helpers (transform kernel) --------
__device__ __forceinline__ unsigned long long dup2(float x) {
    unsigned long long r;
    asm("mov.b64 %0, {%1, %1};" : "=l"(r) : "f"(x));
    return r;
}
__device__ __forceinline__ void ffma2(unsigned long long& d,
                                      unsigned long long a, unsigned long long b) {
    asm("fma.rn.f32x2 %0, %1, %2, %0;" : "+l"(d) : "l"(a), "l"(b));
}
__device__ __forceinline__ float2 unpack2(unsigned long long v) {
    float2 r;
    asm("mov.b64 {%0, %1}, %2;" : "=f"(r.x), "=f"(r.y) : "l"(v));
    return r;
}

// ============================================================
// Kernel 1: H = tanh(X@W+b), Poincare rescale, |h|^2, bf16 hi/lo split out.
// ============================================================
__global__ __launch_bounds__(256, 2)
void transform_kernel(const float* __restrict__ X, const float* __restrict__ W,
                      const float* __restrict__ bias,
                      unsigned* __restrict__ Hhi, unsigned* __restrict__ Hlo,
                      float* __restrict__ SQ, int M)
{
    __shared__ float  Xs[64][17];
    __shared__ float2 Ws2[16][128];
    __shared__ float  s_scale[64];

    const int tid = threadIdx.x;
    const int tx = tid & 15, ty = tid >> 4;
    const int row0 = blockIdx.x * 64;

    unsigned long long acc2[4][8];
#pragma unroll
    for (int i = 0; i < 4; i++)
#pragma unroll
        for (int j = 0; j < 8; j++) acc2[i][j] = 0ull;

    for (int kc = 0; kc < DD; kc += 16) {
#pragma unroll
        for (int e = tid; e < 64 * 16; e += 256) {
            int r = e >> 4, k = e & 15;
            float v = 0.f;
            if (row0 + r < M) v = X[(row0 + r) * DD + kc + k];
            Xs[r][k] = v;
        }
#pragma unroll
        for (int e = tid; e < 16 * 256; e += 256) {
            int k = e >> 8, c = e & 255;
            ((float*)Ws2)[k * 256 + c] = W[(kc + k) * DD + c];
        }
        __syncthreads();
#pragma unroll
        for (int k = 0; k < 16; k++) {
            unsigned long long a2[4], b2[8];
#pragma unroll
            for (int i = 0; i < 4; i++) a2[i] = dup2(Xs[ty + 16 * i][k]);
#pragma unroll
            for (int j = 0; j < 8; j++) {
                float2 bv = Ws2[k][tx + 16 * j];
                b2[j] = *(unsigned long long*)&bv;
            }
#pragma unroll
            for (int i = 0; i < 4; i++)
#pragma unroll
                for (int j = 0; j < 8; j++)
                    ffma2(acc2[i][j], a2[i], b2[j]);
        }
        __syncthreads();
    }

    const float2* bias2 = (const float2*)bias;
    float2 hv[4][8];
    float psum[4];
#pragma unroll
    for (int i = 0; i < 4; i++) {
        psum[i] = 0.f;
#pragma unroll
        for (int j = 0; j < 8; j++) {
            float2 bb = bias2[tx + 16 * j];
            float2 v = unpack2(acc2[i][j]);
            v.x = tanhf(v.x + bb.x);
            v.y = tanhf(v.y + bb.y);
            hv[i][j] = v;
            psum[i] += v.x * v.x + v.y * v.y;
        }
    }
#pragma unroll
    for (int off = 1; off < 16; off <<= 1) {
#pragma unroll
        for (int i = 0; i < 4; i++)
            psum[i] += __shfl_xor_sync(0xffffffffu, psum[i], off);
    }
    if (tx == 0) {
#pragma unroll
        for (int i = 0; i < 4; i++) {
            int r = ty + 16 * i;
            float norm = sqrtf(psum[i]);
            float sc = (norm > 0.95f) ? 0.95f / norm : 1.0f;
            s_scale[r] = sc;
            if (row0 + r < M) SQ[row0 + r] = psum[i] * sc * sc;
        }
    }
    __syncthreads();
#pragma unroll
    for (int i = 0; i < 4; i++) {
        int r = ty + 16 * i;
        if (row0 + r >= M) continue;
        float sc = s_scale[r];
#pragma unroll
        for (int j = 0; j < 8; j++) {
            float2 v = hv[i][j];
            v.x *= sc; v.y *= sc;
            __nv_bfloat16 hx = __float2bfloat16(v.x);
            __nv_bfloat16 hy = __float2bfloat16(v.y);
            __nv_bfloat16 lx = __float2bfloat16(v.x - __bfloat162float(hx));
            __nv_bfloat16 ly = __float2bfloat16(v.y - __bfloat162float(hy));
            size_t o = (size_t)(row0 + r) * 128 + tx + 16 * j;
            Hhi[o] = ((unsigned)__bfloat16_as_ushort(hy) << 16) | __bfloat16_as_ushort(hx);
            Hlo[o] = ((unsigned)__bfloat16_as_ushort(ly) << 16) | __bfloat16_as_ushort(lx);
        }
    }
}

// ============================================================
// Kernel 2: bf16 hi-only mma pruning pass.
// CTA 128q x 64m, 8 warps. Q tile RESIDENT (128x256 hi, 72KB).
// M tiles double-buffered, one sync per k-chunk.
// Selection: per-thread REGISTER top-4 per owned q-row (no smem lists,
// no owner scan, no bank conflicts). 8 threads x 4 = 32 cand/query/split.
// ============================================================
#define RS       144                  // bytes per tile row (ldmatrix conflict-free)
#define QCH_B    (128 * RS)           // 18432 per k-chunk
#define OFF_Q    0                    // 4 chunks resident: 73728
#define OFF_M0   (4 * QCH_B)          // 73728
#define OFF_M1   (OFF_M0 + 64 * RS)   // 82944
#define OFF_YS   (OFF_M1 + 64 * RS)   // 92160 (2 x 64 floats)
#define DSMEM_SZ (OFF_YS + 512)       // 92672

__device__ __forceinline__ void fill_m(char* dst, const uint4* src,
                                       int m0, int c, int mend, int tid) {
#pragma unroll
    for (int it = 0; it < 2; it++) {
        int idx = tid + 256 * it;
        int r = idx >> 3, kb = idx & 7;
        uint4 v = make_uint4(0u, 0u, 0u, 0u);
        if (m0 + r < mend) v = src[(size_t)(m0 + r) * 32 + c * 8 + kb];
        *(uint4*)(dst + r * RS + kb * 16) = v;
    }
}

__device__ __forceinline__ void ins4(float (&la)[4], int (&li)[4],
                                     float& worst, float a, int m) {
    int mp = 0; float mv = la[0];
    if (la[1] > mv) { mv = la[1]; mp = 1; }
    if (la[2] > mv) { mv = la[2]; mp = 2; }
    if (la[3] > mv) { mv = la[3]; mp = 3; }
    la[mp] = a; li[mp] = m;
    mv = la[0];
    if (la[1] > mv) mv = la[1];
    if (la[2] > mv) mv = la[2];
    if (la[3] > mv) mv = la[3];
    worst = mv;
}

__global__ __launch_bounds__(256, 2)
void dist_topk_kernel()
{
    extern __shared__ char sb[];
    const uint32_t sbase = smem_u32(sb);
    float (*tYS)[64] = (float(*)[64])(sb + OFF_YS);

    const int tid = threadIdx.x;
    const int lane = tid & 31;
    const int wid = tid >> 5;
    const int warp_q = wid & 3;
    const int warp_m = wid >> 2;
    const int g4 = lane >> 2;
    const int tg = lane & 3;

    const int q0 = blockIdx.x * 128;
    const int mstart = blockIdx.y * SPLEN;
    const int mend = min(mstart + SPLEN, NM);

    const uint32_t aOff = (uint32_t)((warp_q * 32 + (lane & 7) + ((lane >> 3) & 1) * 8) * RS
                                     + (((lane >> 4) & 1) * 8) * 2);
    const uint32_t bOff = (uint32_t)((warp_m * 32 + (lane & 7) + ((lane >> 4) & 1) * 8) * RS
                                     + (((lane >> 3) & 1) * 8) * 2);
    const uint32_t u_q = sbase + OFF_Q;
    const uint32_t u_m = sbase + OFF_M0;

    float xs[2][2], inv1x[2][2];
#pragma unroll
    for (int i = 0; i < 2; i++)
#pragma unroll
        for (int r = 0; r < 2; r++) {
            float v = g_q_sq[q0 + warp_q * 32 + i * 16 + r * 8 + g4];
            xs[i][r] = v;
            inv1x[i][r] = 1.0f - v;
        }

    // per-thread register top-4 lists, one per owned q-row
    float la[2][2][4];
    int   li[2][2][4];
    float lw[2][2];
#pragma unroll
    for (int i = 0; i < 2; i++)
#pragma unroll
        for (int r = 0; r < 2; r++) {
            lw[i][r] = BIGF;
#pragma unroll
            for (int l = 0; l < 4; l++) { la[i][r][l] = BIGF; li[i][r][l] = NM; }
        }

    // ---- load resident Q tile: 128 rows x 256 k (hi), 4 chunks ----
    {
        const uint4* pQH = (const uint4*)g_q_hi;
#pragma unroll
        for (int it = 0; it < 16; it++) {
            int idx = tid + 256 * it;
            int r = idx >> 5, u = idx & 31;
            int chunk = u >> 3, kb = u & 7;
            uint4 v = pQH[(size_t)(q0 + r) * 32 + u];
            *(uint4*)(sb + OFF_Q + chunk * QCH_B + r * RS + kb * 16) = v;
        }
    }

    const uint4* pMH = (const uint4*)g_mem_hi;
    int par = 0;

    for (int m0 = mstart; m0 < mend; m0 += 64, par ^= 1) {
        if (tid < 64) tYS[par][tid] = (m0 + tid < mend) ? g_mem_sq[m0 + tid] : 0.f;
        fill_m(sb + OFF_M0, pMH, m0, 0, mend, tid);
        __syncthreads();

        float acc[2][4][4];
#pragma unroll
        for (int i = 0; i < 2; i++)
#pragma unroll
            for (int j = 0; j < 4; j++)
#pragma unroll
                for (int c = 0; c < 4; c++) acc[i][j][c] = 0.f;

#pragma unroll
        for (int c = 0; c < 4; c++) {
            if (c < 3)
                fill_m(sb + OFF_M0 + ((c + 1) & 1) * (64 * RS), pMH, m0, c + 1, mend, tid);

            const uint32_t aBase = u_q + c * QCH_B + aOff;
            const uint32_t bBase = u_m + (c & 1) * (64 * RS) + bOff;
#pragma unroll
            for (int ks = 0; ks < 4; ks++) {
                uint32_t ah[2][4], bh[2][4];
#pragma unroll
                for (int i = 0; i < 2; i++)
                    LDSM_X4(ah[i][0], ah[i][1], ah[i][2], ah[i][3],
                            aBase + ks * 32 + i * (16 * RS));
#pragma unroll
                for (int jj = 0; jj < 2; jj++)
                    LDSM_X4(bh[jj][0], bh[jj][1], bh[jj][2], bh[jj][3],
                            bBase + ks * 32 + jj * (16 * RS));
#pragma unroll
                for (int i = 0; i < 2; i++)
#pragma unroll
                    for (int j = 0; j < 4; j++) {
                        int jj = j >> 1, s = (j & 1) * 2;
                        mma_bf16(acc[i][j], ah[i], bh[jj][s], bh[jj][s + 1]);
                    }
            }
            __syncthreads();
        }

        // ---- epilogue: pure-register top-4 maintenance ----
#pragma unroll
        for (int i = 0; i < 2; i++)
#pragma unroll
            for (int r = 0; r < 2; r++) {
                float xsi = xs[i][r], inv = inv1x[i][r];
#pragma unroll
                for (int j = 0; j < 4; j++) {
                    int ml = warp_m * 32 + j * 8 + 2 * tg;
                    int mA = m0 + ml;
                    float dA = acc[i][j][r * 2 + 0];
                    float dB = acc[i][j][r * 2 + 1];
                    float yA = tYS[par][ml], yB = tYS[par][ml + 1];
                    float d2A = fmaxf(xsi + yA - 2.f * dA, 0.f);
                    float d2B = fmaxf(xsi + yB - 2.f * dB, 0.f);
                    float argA = 1.f + 2.f * d2A / (inv * (1.f - yA) + 1e-8f);
                    float argB = 1.f + 2.f * d2B / (inv * (1.f - yB) + 1e-8f);
                    if (mA < mend && argA < lw[i][r])
                        ins4(la[i][r], li[i][r], lw[i][r], argA, mA);
                    if (mA + 1 < mend && argB < lw[i][r])
                        ins4(la[i][r], li[i][r], lw[i][r], argB, mA + 1);
                }
            }
    }

    // ---- write per-thread lists straight to global candidates ----
#pragma unroll
    for (int i = 0; i < 2; i++)
#pragma unroll
        for (int r = 0; r < 2; r++) {
            int q = q0 + warp_q * 32 + i * 16 + r * 8 + g4;
            int base = (q * NSPLIT + blockIdx.y) * CPS + (warp_m * 4 + tg) * 4;
#pragma unroll
            for (int l = 0; l < 4; l++) {
                g_cand_arg[base + l] = la[i][r][l];
                g_cand_idx[base + l] = li[i][r][l];
            }
        }
}

// ============================================================
// Kernel 3: approx top-8 -> threshold prune -> EXACT fp32 rerank -> softmax.
// ============================================================
__global__ void merge_kernel(const float* __restrict__ masks, float* __restrict__ out)
{
    __shared__ float ca[NC2];
    __shared__ int   ci[NC2];
    __shared__ float qf[DD];
    __shared__ int   ridx[RCAP];
    __shared__ float ra[RCAP];
    __shared__ float wa[8];
    __shared__ int   wi[8], wp[8];
    __shared__ float sel_a[KSEL];
    __shared__ int   sel_i[KSEL];
    __shared__ int   rpos[KSEL];
    __shared__ float rval[KSEL];
    __shared__ int   scnt;

    const int q = blockIdx.x;
    const int tid = threadIdx.x;
    const int lane = tid & 31, wid = tid >> 5;

    if (tid == 0) scnt = 0;
    for (int c = tid; c < NC2; c += 256) {
        float a = g_cand_arg[q * NC2 + c];
        ca[c] = (a < BIGF) ? fmaxf(a, 1.0f + 1e-6f) : BIGF;
        ci[c] = g_cand_idx[q * NC2 + c];
    }
    if (tid < 128) {
        unsigned h = g_q_hi[q * 128 + tid];
        unsigned l = g_q_lo[q * 128 + tid];
        qf[2 * tid + 0] = bflo(h) + bflo(l);
        qf[2 * tid + 1] = bfhi(h) + bfhi(l);
    }
    __syncthreads();

    // ---- approx top-8 (threshold anchor) ----
    for (int r = 0; r < KSEL; r++) {
        float ba = BIGF; int bi = 0x7fffffff, bp = 0;
        for (int c = tid; c < NC2; c += 256) {
            float a = ca[c]; int i = ci[c];
            if (a < ba || (a == ba && i < bi)) { ba = a; bi = i; bp = c; }
        }
#pragma unroll
        for (int off = 16; off; off >>= 1) {
            float oa = __shfl_down_sync(0xffffffffu, ba, off);
            int oi = __shfl_down_sync(0xffffffffu, bi, off);
            int op = __shfl_down_sync(0xffffffffu, bp, off);
            if (oa < ba || (oa == ba && oi < bi)) { ba = oa; bi = oi; bp = op; }
        }
        if (lane == 0) { wa[wid] = ba; wi[wid] = bi; wp[wid] = bp; }
        __syncthreads();
        if (tid == 0) {
            float fa = wa[0]; int fi = wi[0], fp = wp[0];
#pragma unroll
            for (int w = 1; w < 8; w++) {
                if (wa[w] < fa || (wa[w] == fa && wi[w] < fi)) {
                    fa = wa[w]; fi = wi[w]; fp = wp[w];
                }
            }
            sel_a[r] = fa; rpos[r] = fp; rval[r] = fa;
            ca[fp] = BIGF;
        }
        __syncthreads();
    }
    if (tid < KSEL) ca[rpos[tid]] = rval[tid];
    __syncthreads();

    // ---- refine list: everything within MARGIN of approx 8th ----
    const float thresh = sel_a[KSEL - 1] + MARGIN;
    for (int c = tid; c < NC2; c += 256) {
        if (ca[c] <= thresh && (unsigned)ci[c] < NM) {
            int p = atomicAdd(&scnt, 1);
            if (p < RCAP) ridx[p] = ci[c];
        }
    }
    __syncthreads();
    const int cnt = min(scnt, RCAP);
    const float x_sq = g_q_sq[q];
    const float invx = 1.0f - x_sq;

    // ---- exact fp32 dots for refine candidates (warp per candidate) ----
    for (int c = wid; c < cnt; c += 8) {
        int m = ridx[c];
        const uint4* ph = (const uint4*)(g_mem_hi + (size_t)m * 128);
        const uint4* pl = (const uint4*)(g_mem_lo + (size_t)m * 128);
        uint4 h = ph[lane], l = pl[lane];
        const float* qp = &qf[lane * 8];
        float dot;
        dot  = (bflo(h.x) + bflo(l.x)) * qp[0];
        dot += (bfhi(h.x) + bfhi(l.x)) * qp[1];
        dot += (bflo(h.y) + bflo(l.y)) * qp[2];
        dot += (bfhi(h.y) + bfhi(l.y)) * qp[3];
        dot += (bflo(h.z) + bflo(l.z)) * qp[4];
        dot += (bfhi(h.z) + bfhi(l.z)) * qp[5];
        dot += (bflo(h.w) + bflo(l.w)) * qp[6];
        dot += (bfhi(h.w) + bfhi(l.w)) * qp[7];
#pragma unroll
        for (int off = 16; off; off >>= 1)
            dot += __shfl_xor_sync(0xffffffffu, dot, off);
        if (lane == 0) {
            float ysq = g_mem_sq[m];
            float d2 = fmaxf(x_sq + ysq - 2.f * dot, 0.f);
            float arg = 1.f + 2.f * d2 / (invx * (1.f - ysq) + 1e-8f);
            ra[c] = fmaxf(arg, 1.0f + 1e-6f);
        }
    }
    __syncthreads();

    // ---- final exact top-8 (warp 0) ----
    if (wid == 0) {
        for (int r = 0; r < KSEL; r++) {
            float ba = BIGF; int bi = 0x7fffffff, bp = 0;
            for (int c = lane; c < cnt; c += 32) {
                float a = ra[c]; int i = ridx[c];
                if (a < ba || (a == ba && i < bi)) { ba = a; bi = i; bp = c; }
            }
#pragma unroll
            for (int off = 16; off; off >>= 1) {
                float oa = __shfl_down_sync(0xffffffffu, ba, off);
                int oi = __shfl_down_sync(0xffffffffu, bi, off);
                int op = __shfl_down_sync(0xffffffffu, bp, off);
                if (oa < ba || (oa == ba && oi < bi)) { ba = oa; bi = oi; bp = op; }
            }
            ba = __shfl_sync(0xffffffffu, ba, 0);
            bi = __shfl_sync(0xffffffffu, bi, 0);
            bp = __shfl_sync(0xffffffffu, bp, 0);
            if (lane == 0) {
                sel_a[r] = ba; sel_i[r] = bi;
                ra[bp] = BIGF;
            }
            __syncwarp();
        }
    }
    __syncthreads();

    if (tid == 0) {
        float d[KSEL];
#pragma unroll
        for (int s = 0; s < KSEL; s++) d[s] = acoshf(sel_a[s]);
        float d0 = d[0];
        float e[KSEL], sum = 0.f;
#pragma unroll
        for (int s = 0; s < KSEL; s++) { e[s] = expf(d0 - d[s]); sum += e[s]; }
        float inv = 1.0f / sum;
#pragma unroll
        for (int s = 0; s < KSEL; s++) out[q * KSEL + s] = e[s] * inv;
    }
    __syncthreads();

    float4* hout = (float4*)(out + (size_t)BQ * KSEL);
    for (int e = tid; e < KSEL * (MAXA / 4); e += 256) {
        int s = e / (MAXA / 4), a4 = e - s * (MAXA / 4);
        const float4* src = (const float4*)(masks + (size_t)sel_i[s] * MAXA);
        hout[((size_t)q * KSEL + s) * (MAXA / 4) + a4] = src[a4];
    }
}

// ============================================================
extern "C" void kernel_launch(void* const* d_in, const int* in_sizes, int n_in,
                              void* d_out, int out_size)
{
    (void)in_sizes; (void)n_in; (void)out_size;
    const float* q_emb  = (const float*)d_in[0];
    const float* m_emb  = (const float*)d_in[1];
    const float* masks  = (const float*)d_in[2];
    const float* W      = (const float*)d_in[3];
    const float* bias   = (const float*)d_in[4];
    float* out = (float*)d_out;

    unsigned *d_mhi, *d_mlo, *d_qhi, *d_qlo;
    float *d_msq, *d_qsq;
    cudaGetSymbolAddress((void**)&d_mhi, g_mem_hi);
    cudaGetSymbolAddress((void**)&d_mlo, g_mem_lo);
    cudaGetSymbolAddress((void**)&d_qhi, g_q_hi);
    cudaGetSymbolAddress((void**)&d_qlo, g_q_lo);
    cudaGetSymbolAddress((void**)&d_msq, g_mem_sq);
    cudaGetSymbolAddress((void**)&d_qsq, g_q_sq);

    cudaFuncSetAttribute(dist_topk_kernel,
                         cudaFuncAttributeMaxDynamicSharedMemorySize, DSMEM_SZ);

    transform_kernel<<<(NM + 63) / 64, 256>>>(m_emb, W, bias, d_mhi, d_mlo, d_msq, NM);
    transform_kernel<<<(BQ + 63) / 64, 256>>>(q_emb, W, bias, d_qhi, d_qlo, d_qsq, BQ);

    dim3 g2(BQ / 128, NSPLIT);
    dist_topk_kernel<<<g2, 256, DSMEM_SZ>>>();

    merge_kernel<<<BQ, 256>>>(masks, out);
}

// round 11
// speedup vs baseline: 1.6717x; 1.2109x over previous
#include <cuda_runtime.h>
#include <cuda_bf16.h>
#include <math.h>
#include <stdint.h>

#define BQ    1024
#define NM    50000
#define DD    256
#define MAXA  200
#define KSEL  8
#define NSPLIT 37
#define SPLEN  1352            // ceil(50000/37)
#define CPS   32               // candidates per (query, split): 8 threads x top-4
#define NC2   (NSPLIT*CPS)     // 1184 candidates per query at merge
#define RCAP  64               // refine-list capacity
#define MARGIN 4.25f           // approx err (~1.5) *2 + quantization slack
#define BIGF  3.0e38f

// -------- device scratch --------
__device__ unsigned g_mem_hi[NM * 128];   // bf16x2: col pair per u32
__device__ unsigned g_mem_lo[NM * 128];
__device__ unsigned g_q_hi[BQ * 128];
__device__ unsigned g_q_lo[BQ * 128];
__device__ float    g_mem_sq[NM];
__device__ float    g_q_sq[BQ];
__device__ uint32_t g_cand[BQ * NC2];     // packed: arg-bits[31:11] | m_rel[10:0]

// ===================== PTX helpers =====================
__device__ __forceinline__ uint32_t smem_u32(const void* p) {
    uint32_t a;
    asm("{ .reg .u64 t; cvta.to.shared.u64 t, %1; cvt.u32.u64 %0, t; }" : "=r"(a) : "l"(p));
    return a;
}
#define LDSM_X4(r0, r1, r2, r3, addr) \
    asm volatile("ldmatrix.sync.aligned.m8n8.x4.shared.b16 {%0,%1,%2,%3}, [%4];" \
        : "=r"(r0), "=r"(r1), "=r"(r2), "=r"(r3) : "r"(addr))

__device__ __forceinline__ void mma_bf16(float* c, const uint32_t* a,
                                         uint32_t b0, uint32_t b1) {
    asm volatile("mma.sync.aligned.m16n8k16.row.col.f32.bf16.bf16.f32 "
        "{%0,%1,%2,%3},{%4,%5,%6,%7},{%8,%9},{%0,%1,%2,%3};"
        : "+f"(c[0]), "+f"(c[1]), "+f"(c[2]), "+f"(c[3])
        : "r"(a[0]), "r"(a[1]), "r"(a[2]), "r"(a[3]), "r"(b0), "r"(b1));
}

// bf16x2 unpack: even dim in low 16 bits, odd dim in high 16 bits
__device__ __forceinline__ float bflo(uint32_t v) { return __uint_as_float(v << 16); }
__device__ __forceinline__ float bfhi(uint32_t v) { return __uint_as_float(v & 0xffff0000u); }

// -------- packed f32x2 helpers (transform kernel) --------
__device__ __forceinline__ unsigned long long dup2(float x) {
    unsigned long long r;
    asm("mov.b64 %0, {%1, %1};" : "=l"(r) : "f"(x));
    return r;
}
__device__ __forceinline__ void ffma2(unsigned long long& d,
                                      unsigned long long a, unsigned long long b) {
    asm("fma.rn.f32x2 %0, %1, %2, %0;" : "+l"(d) : "l"(a), "l"(b));
}
__device__ __forceinline__ float2 unpack2(unsigned long long v) {
    float2 r;
    asm("mov.b64 {%0, %1}, %2;" : "=f"(r.x), "=f"(r.y) : "l"(v));
    return r;
}

// ============================================================
// Kernel 1: H = tanh(X@W+b), Poincare rescale, |h|^2, bf16 hi/lo split out.
// (unchanged from R10 — passing)
// ============================================================
__global__ __launch_bounds__(256, 2)
void transform_kernel(const float* __restrict__ X, const float* __restrict__ W,
                      const float* __restrict__ bias,
                      unsigned* __restrict__ Hhi, unsigned* __restrict__ Hlo,
                      float* __restrict__ SQ, int M)
{
    __shared__ float  Xs[64][17];
    __shared__ float2 Ws2[16][128];
    __shared__ float  s_scale[64];

    const int tid = threadIdx.x;
    const int tx = tid & 15, ty = tid >> 4;
    const int row0 = blockIdx.x * 64;

    unsigned long long acc2[4][8];
#pragma unroll
    for (int i = 0; i < 4; i++)
#pragma unroll
        for (int j = 0; j < 8; j++) acc2[i][j] = 0ull;

    for (int kc = 0; kc < DD; kc += 16) {
#pragma unroll
        for (int e = tid; e < 64 * 16; e += 256) {
            int r = e >> 4, k = e & 15;
            float v = 0.f;
            if (row0 + r < M) v = X[(row0 + r) * DD + kc + k];
            Xs[r][k] = v;
        }
#pragma unroll
        for (int e = tid; e < 16 * 256; e += 256) {
            int k = e >> 8, c = e & 255;
            ((float*)Ws2)[k * 256 + c] = W[(kc + k) * DD + c];
        }
        __syncthreads();
#pragma unroll
        for (int k = 0; k < 16; k++) {
            unsigned long long a2[4], b2[8];
#pragma unroll
            for (int i = 0; i < 4; i++) a2[i] = dup2(Xs[ty + 16 * i][k]);
#pragma unroll
            for (int j = 0; j < 8; j++) {
                float2 bv = Ws2[k][tx + 16 * j];
                b2[j] = *(unsigned long long*)&bv;
            }
#pragma unroll
            for (int i = 0; i < 4; i++)
#pragma unroll
                for (int j = 0; j < 8; j++)
                    ffma2(acc2[i][j], a2[i], b2[j]);
        }
        __syncthreads();
    }

    const float2* bias2 = (const float2*)bias;
    float2 hv[4][8];
    float psum[4];
#pragma unroll
    for (int i = 0; i < 4; i++) {
        psum[i] = 0.f;
#pragma unroll
        for (int j = 0; j < 8; j++) {
            float2 bb = bias2[tx + 16 * j];
            float2 v = unpack2(acc2[i][j]);
            v.x = tanhf(v.x + bb.x);
            v.y = tanhf(v.y + bb.y);
            hv[i][j] = v;
            psum[i] += v.x * v.x + v.y * v.y;
        }
    }
#pragma unroll
    for (int off = 1; off < 16; off <<= 1) {
#pragma unroll
        for (int i = 0; i < 4; i++)
            psum[i] += __shfl_xor_sync(0xffffffffu, psum[i], off);
    }
    if (tx == 0) {
#pragma unroll
        for (int i = 0; i < 4; i++) {
            int r = ty + 16 * i;
            float norm = sqrtf(psum[i]);
            float sc = (norm > 0.95f) ? 0.95f / norm : 1.0f;
            s_scale[r] = sc;
            if (row0 + r < M) SQ[row0 + r] = psum[i] * sc * sc;
        }
    }
    __syncthreads();
#pragma unroll
    for (int i = 0; i < 4; i++) {
        int r = ty + 16 * i;
        if (row0 + r >= M) continue;
        float sc = s_scale[r];
#pragma unroll
        for (int j = 0; j < 8; j++) {
            float2 v = hv[i][j];
            v.x *= sc; v.y *= sc;
            __nv_bfloat16 hx = __float2bfloat16(v.x);
            __nv_bfloat16 hy = __float2bfloat16(v.y);
            __nv_bfloat16 lx = __float2bfloat16(v.x - __bfloat162float(hx));
            __nv_bfloat16 ly = __float2bfloat16(v.y - __bfloat162float(hy));
            size_t o = (size_t)(row0 + r) * 128 + tx + 16 * j;
            Hhi[o] = ((unsigned)__bfloat16_as_ushort(hy) << 16) | __bfloat16_as_ushort(hx);
            Hlo[o] = ((unsigned)__bfloat16_as_ushort(ly) << 16) | __bfloat16_as_ushort(lx);
        }
    }
}

// ============================================================
// Kernel 2: bf16 hi-only mma pruning pass.
// Q resident (4 chunks, 72KB). ALL 4 M chunks resident per block
// (batched LDG, 2 syncs/block). Division-free epilogue via rY[] table.
// Per-thread register top-4 of PACKED u32 (argbits|mrel) per owned q-row.
// ============================================================
#define RS       144                  // bytes per tile row (ldmatrix conflict-free)
#define QCH_B    (128 * RS)           // 18432 per k-chunk
#define MCH_B    (64 * RS)            // 9216 per k-chunk
#define OFF_Q    0                    // 4 chunks: 73728
#define OFF_M    (4 * QCH_B)          // 73728, 4 chunks: 36864
#define OFF_YS   (OFF_M + 4 * MCH_B)  // 110592
#define OFF_RY   (OFF_YS + 256)       // 110848
#define DSMEM_SZ (OFF_RY + 256)       // 111104 (x2 CTAs = 222KB <= 228KB)

__device__ __forceinline__ void ins4u(uint32_t (&la)[4], uint32_t& worst, uint32_t pk) {
    int mp = 0; uint32_t mv = la[0];
    if (la[1] > mv) { mv = la[1]; mp = 1; }
    if (la[2] > mv) { mv = la[2]; mp = 2; }
    if (la[3] > mv) { mv = la[3]; mp = 3; }
    la[mp] = pk;
    mv = la[0];
    if (la[1] > mv) mv = la[1];
    if (la[2] > mv) mv = la[2];
    if (la[3] > mv) mv = la[3];
    worst = mv;
}

__global__ __launch_bounds__(256, 2)
void dist_topk_kernel()
{
    extern __shared__ char sb[];
    const uint32_t sbase = smem_u32(sb);
    float* tYS = (float*)(sb + OFF_YS);
    float* tRY = (float*)(sb + OFF_RY);

    const int tid = threadIdx.x;
    const int lane = tid & 31;
    const int wid = tid >> 5;
    const int warp_q = wid & 3;
    const int warp_m = wid >> 2;
    const int g4 = lane >> 2;
    const int tg = lane & 3;

    const int q0 = blockIdx.x * 128;
    const int mstart = blockIdx.y * SPLEN;
    const int mend = min(mstart + SPLEN, NM);

    const uint32_t aOff = (uint32_t)((warp_q * 32 + (lane & 7) + ((lane >> 3) & 1) * 8) * RS
                                     + (((lane >> 4) & 1) * 8) * 2);
    const uint32_t bOff = (uint32_t)((warp_m * 32 + (lane & 7) + ((lane >> 4) & 1) * 8) * RS
                                     + (((lane >> 3) & 1) * 8) * 2);
    const uint32_t u_q = sbase + OFF_Q;
    const uint32_t u_m = sbase + OFF_M;

    float xs[2][2], cA[2][2];
#pragma unroll
    for (int i = 0; i < 2; i++)
#pragma unroll
        for (int r = 0; r < 2; r++) {
            float v = g_q_sq[q0 + warp_q * 32 + i * 16 + r * 8 + g4];
            xs[i][r] = v;
            cA[i][r] = 2.0f / (1.0f - v);
        }

    // per-thread packed top-4 lists, one per owned q-row
    uint32_t la[2][2][4];
    uint32_t lw[2][2];
#pragma unroll
    for (int i = 0; i < 2; i++)
#pragma unroll
        for (int r = 0; r < 2; r++) {
            lw[i][r] = 0xFFFFFFFFu;
#pragma unroll
            for (int l = 0; l < 4; l++) la[i][r][l] = 0xFFFFFFFFu;
        }

    // ---- load resident Q tile: 128 rows x 256 k (hi), 4 chunks ----
    {
        const uint4* pQH = (const uint4*)g_q_hi;
#pragma unroll
        for (int it = 0; it < 16; it++) {
            int idx = tid + 256 * it;
            int r = idx >> 5, u = idx & 31;
            int chunk = u >> 3, kb = u & 7;
            uint4 v = pQH[(size_t)(q0 + r) * 32 + u];
            *(uint4*)(sb + OFF_Q + chunk * QCH_B + r * RS + kb * 16) = v;
        }
    }

    const uint4* pMH = (const uint4*)g_mem_hi;

    for (int m0 = mstart; m0 < mend; m0 += 64) {
        __syncthreads();   // prev block's mma/epilogue done before refill

        if (tid < 64) {
            int m = m0 + tid;
            float ys = (m < mend) ? g_mem_sq[m] : 0.f;
            tYS[tid] = ys;
            tRY[tid] = __frcp_rn(1.0f - ys);
        }
        // fill all 4 M chunks (batched LDG, MLP 8)
#pragma unroll
        for (int it = 0; it < 8; it++) {
            int idx = tid + 256 * it;
            int r = idx >> 5, u = idx & 31;
            int chunk = u >> 3, kb = u & 7;
            uint4 v = make_uint4(0u, 0u, 0u, 0u);
            if (m0 + r < mend) v = pMH[(size_t)(m0 + r) * 32 + u];
            *(uint4*)(sb + OFF_M + chunk * MCH_B + r * RS + kb * 16) = v;
        }
        __syncthreads();

        float acc[2][4][4];
#pragma unroll
        for (int i = 0; i < 2; i++)
#pragma unroll
            for (int j = 0; j < 4; j++)
#pragma unroll
                for (int c = 0; c < 4; c++) acc[i][j][c] = 0.f;

#pragma unroll
        for (int c = 0; c < 4; c++) {
            const uint32_t aBase = u_q + c * QCH_B + aOff;
            const uint32_t bBase = u_m + c * MCH_B + bOff;
#pragma unroll
            for (int ks = 0; ks < 4; ks++) {
                uint32_t ah[2][4], bh[2][4];
#pragma unroll
                for (int i = 0; i < 2; i++)
                    LDSM_X4(ah[i][0], ah[i][1], ah[i][2], ah[i][3],
                            aBase + ks * 32 + i * (16 * RS));
#pragma unroll
                for (int jj = 0; jj < 2; jj++)
                    LDSM_X4(bh[jj][0], bh[jj][1], bh[jj][2], bh[jj][3],
                            bBase + ks * 32 + jj * (16 * RS));
#pragma unroll
                for (int i = 0; i < 2; i++)
#pragma unroll
                    for (int j = 0; j < 4; j++) {
                        int jj = j >> 1, s = (j & 1) * 2;
                        mma_bf16(acc[i][j], ah[i], bh[jj][s], bh[jj][s + 1]);
                    }
            }
        }

        // ---- epilogue: division-free t = d2 * cA * rY, packed insert ----
        const int m0rel = m0 - mstart;
#pragma unroll
        for (int i = 0; i < 2; i++)
#pragma unroll
            for (int r = 0; r < 2; r++) {
                float xsi = xs[i][r], cc = cA[i][r];
#pragma unroll
                for (int j = 0; j < 4; j++) {
                    int ml = warp_m * 32 + j * 8 + 2 * tg;
                    int mA = m0 + ml;
                    float dA = acc[i][j][r * 2 + 0];
                    float dB = acc[i][j][r * 2 + 1];
                    float d2A = fmaxf(fmaf(-2.f, dA, xsi + tYS[ml]), 0.f);
                    float d2B = fmaxf(fmaf(-2.f, dB, xsi + tYS[ml + 1]), 0.f);
                    float tA = d2A * cc * tRY[ml];
                    float tB = d2B * cc * tRY[ml + 1];
                    uint32_t pkA = (__float_as_uint(tA) & 0xFFFFF800u)
                                   | (uint32_t)(m0rel + ml);
                    uint32_t pkB = (__float_as_uint(tB) & 0xFFFFF800u)
                                   | (uint32_t)(m0rel + ml + 1);
                    if (mA < mend && pkA < lw[i][r]) ins4u(la[i][r], lw[i][r], pkA);
                    if (mA + 1 < mend && pkB < lw[i][r]) ins4u(la[i][r], lw[i][r], pkB);
                }
            }
    }

    // ---- write per-thread packed lists to global candidates ----
#pragma unroll
    for (int i = 0; i < 2; i++)
#pragma unroll
        for (int r = 0; r < 2; r++) {
            int q = q0 + warp_q * 32 + i * 16 + r * 8 + g4;
            int base = (q * NSPLIT + blockIdx.y) * CPS + (warp_m * 4 + tg) * 4;
#pragma unroll
            for (int l = 0; l < 4; l++)
                g_cand[base + l] = la[i][r][l];
        }
}

// ============================================================
// Kernel 3: per-warp top-8 (u32 domain) -> threshold -> refine list ->
// EXACT fp32 rerank -> softmax -> gather.
// ============================================================
__device__ __forceinline__ float dec_t(uint32_t v) {
    return __uint_as_float(v & 0xFFFFF800u);
}

__global__ void merge_kernel(const float* __restrict__ masks, float* __restrict__ out)
{
    __shared__ uint32_t cv[NC2];
    __shared__ uint32_t w8[8][8];
    __shared__ float qf[DD];
    __shared__ int   ridx[RCAP];
    __shared__ float ra[RCAP];
    __shared__ float sel_a[KSEL];
    __shared__ int   sel_i[KSEL];
    __shared__ float s_thresh;
    __shared__ int   scnt;

    const int q = blockIdx.x;
    const int tid = threadIdx.x;
    const int lane = tid & 31, wid = tid >> 5;

    if (tid == 0) scnt = 0;
    for (int c = tid; c < NC2; c += 256) cv[c] = g_cand[q * NC2 + c];
    if (tid < 128) {
        unsigned h = g_q_hi[q * 128 + tid];
        unsigned l = g_q_lo[q * 128 + tid];
        qf[2 * tid + 0] = bflo(h) + bflo(l);
        qf[2 * tid + 1] = bfhi(h) + bfhi(l);
    }
    __syncthreads();

    // ---- per-warp top-8 over its 148 candidates (no block syncs) ----
    {
        const int wbase = wid * 148;
        uint32_t v[5];
#pragma unroll
        for (int k = 0; k < 5; k++) {
            int c = wbase + lane + 32 * k;
            v[k] = (lane + 32 * k < 148) ? cv[c] : 0xFFFFFFFFu;
        }
#pragma unroll
        for (int r = 0; r < 8; r++) {
            uint32_t lmin = v[0]; int pos = 0;
#pragma unroll
            for (int k = 1; k < 5; k++)
                if (v[k] < lmin) { lmin = v[k]; pos = k; }
            uint32_t rmin = lmin;
#pragma unroll
            for (int off = 16; off; off >>= 1)
                rmin = min(rmin, __shfl_xor_sync(0xffffffffu, rmin, off));
            unsigned ball = __ballot_sync(0xffffffffu, lmin == rmin);
            if (lane == (int)(__ffs(ball) - 1)) v[pos] = 0xFFFFFFFFu;
            if (lane == 0) w8[wid][r] = rmin;
        }
    }
    __syncthreads();

    // ---- 8th smallest of the 64 union entries -> threshold ----
    if (tid == 0) {
        uint32_t u[64];
#pragma unroll
        for (int e = 0; e < 64; e++) u[e] = ((uint32_t*)w8)[e];
        uint32_t e8 = 0;
        for (int r = 0; r < 8; r++) {
            uint32_t mn = 0xFFFFFFFFu; int mp = 0;
            for (int e = 0; e < 64; e++)
                if (u[e] < mn) { mn = u[e]; mp = e; }
            u[mp] = 0xFFFFFFFFu;
            e8 = mn;
        }
        s_thresh = 1.0f + dec_t(e8) + MARGIN;
    }
    __syncthreads();

    // ---- refine list: decode + threshold ----
    const float thresh = s_thresh;
    for (int c = tid; c < NC2; c += 256) {
        uint32_t pv = cv[c];
        float t = dec_t(pv);
        if (1.0f + t <= thresh) {
            int idx = (c >> 5) * SPLEN + (int)(pv & 0x7FFu);
            if (idx < NM) {
                int p = atomicAdd(&scnt, 1);
                if (p < RCAP) ridx[p] = idx;
            }
        }
    }
    __syncthreads();
    const int cnt = min(scnt, RCAP);
    const float x_sq = g_q_sq[q];
    const float invx = 1.0f - x_sq;

    // ---- exact fp32 dots for refine candidates (warp per candidate) ----
    for (int c = wid; c < cnt; c += 8) {
        int m = ridx[c];
        const uint4* ph = (const uint4*)(g_mem_hi + (size_t)m * 128);
        const uint4* pl = (const uint4*)(g_mem_lo + (size_t)m * 128);
        uint4 h = ph[lane], l = pl[lane];
        const float* qp = &qf[lane * 8];
        float dot;
        dot  = (bflo(h.x) + bflo(l.x)) * qp[0];
        dot += (bfhi(h.x) + bfhi(l.x)) * qp[1];
        dot += (bflo(h.y) + bflo(l.y)) * qp[2];
        dot += (bfhi(h.y) + bfhi(l.y)) * qp[3];
        dot += (bflo(h.z) + bflo(l.z)) * qp[4];
        dot += (bfhi(h.z) + bfhi(l.z)) * qp[5];
        dot += (bflo(h.w) + bflo(l.w)) * qp[6];
        dot += (bfhi(h.w) + bfhi(l.w)) * qp[7];
#pragma unroll
        for (int off = 16; off; off >>= 1)
            dot += __shfl_xor_sync(0xffffffffu, dot, off);
        if (lane == 0) {
            float ysq = g_mem_sq[m];
            float d2 = fmaxf(x_sq + ysq - 2.f * dot, 0.f);
            float arg = 1.f + 2.f * d2 / (invx * (1.f - ysq) + 1e-8f);
            ra[c] = fmaxf(arg, 1.0f + 1e-6f);
        }
    }
    __syncthreads();

    // ---- final exact top-8 (warp 0), lexicographic (arg, idx) ----
    if (wid == 0) {
        for (int r = 0; r < KSEL; r++) {
            float ba = BIGF; int bi = 0x7fffffff, bp = 0;
            for (int c = lane; c < cnt; c += 32) {
                float a = ra[c]; int i = ridx[c];
                if (a < ba || (a == ba && i < bi)) { ba = a; bi = i; bp = c; }
            }
#pragma unroll
            for (int off = 16; off; off >>= 1) {
                float oa = __shfl_down_sync(0xffffffffu, ba, off);
                int oi = __shfl_down_sync(0xffffffffu, bi, off);
                int op = __shfl_down_sync(0xffffffffu, bp, off);
                if (oa < ba || (oa == ba && oi < bi)) { ba = oa; bi = oi; bp = op; }
            }
            ba = __shfl_sync(0xffffffffu, ba, 0);
            bi = __shfl_sync(0xffffffffu, bi, 0);
            bp = __shfl_sync(0xffffffffu, bp, 0);
            if (lane == 0) {
                sel_a[r] = ba; sel_i[r] = bi;
                ra[bp] = BIGF;
            }
            __syncwarp();
        }
    }
    __syncthreads();

    if (tid == 0) {
        float d[KSEL];
#pragma unroll
        for (int s = 0; s < KSEL; s++) d[s] = acoshf(sel_a[s]);
        float d0 = d[0];
        float e[KSEL], sum = 0.f;
#pragma unroll
        for (int s = 0; s < KSEL; s++) { e[s] = expf(d0 - d[s]); sum += e[s]; }
        float inv = 1.0f / sum;
#pragma unroll
        for (int s = 0; s < KSEL; s++) out[q * KSEL + s] = e[s] * inv;
    }
    __syncthreads();

    float4* hout = (float4*)(out + (size_t)BQ * KSEL);
    for (int e = tid; e < KSEL * (MAXA / 4); e += 256) {
        int s = e / (MAXA / 4), a4 = e - s * (MAXA / 4);
        const float4* src = (const float4*)(masks + (size_t)sel_i[s] * MAXA);
        hout[((size_t)q * KSEL + s) * (MAXA / 4) + a4] = src[a4];
    }
}

// ============================================================
extern "C" void kernel_launch(void* const* d_in, const int* in_sizes, int n_in,
                              void* d_out, int out_size)
{
    (void)in_sizes; (void)n_in; (void)out_size;
    const float* q_emb  = (const float*)d_in[0];
    const float* m_emb  = (const float*)d_in[1];
    const float* masks  = (const float*)d_in[2];
    const float* W      = (const float*)d_in[3];
    const float* bias   = (const float*)d_in[4];
    float* out = (float*)d_out;

    unsigned *d_mhi, *d_mlo, *d_qhi, *d_qlo;
    float *d_msq, *d_qsq;
    cudaGetSymbolAddress((void**)&d_mhi, g_mem_hi);
    cudaGetSymbolAddress((void**)&d_mlo, g_mem_lo);
    cudaGetSymbolAddress((void**)&d_qhi, g_q_hi);
    cudaGetSymbolAddress((void**)&d_qlo, g_q_lo);
    cudaGetSymbolAddress((void**)&d_msq, g_mem_sq);
    cudaGetSymbolAddress((void**)&d_qsq, g_q_sq);

    cudaFuncSetAttribute(dist_topk_kernel,
                         cudaFuncAttributeMaxDynamicSharedMemorySize, DSMEM_SZ);

    transform_kernel<<<(NM + 63) / 64, 256>>>(m_emb, W, bias, d_mhi, d_mlo, d_msq, NM);
    transform_kernel<<<(BQ + 63) / 64, 256>>>(q_emb, W, bias, d_qhi, d_qlo, d_qsq, BQ);

    dim3 g2(BQ / 128, NSPLIT);
    dist_topk_kernel<<<g2, 256, DSMEM_SZ>>>();

    merge_kernel<<<BQ, 256>>>(masks, out);
}

// round 14
// speedup vs baseline: 1.6938x; 1.0132x over previous
#include <cuda_runtime.h>
#include <cuda_bf16.h>
#include <math.h>
#include <stdint.h>

#define BQ    1024
#define NM    50000
#define DD    256
#define MAXA  200
#define KSEL  8
#define NSPLIT 37
#define SPLEN  1352            // ceil(50000/37)
#define CPS   32               // candidates per (query, split): 8 threads x top-4
#define NC2   (NSPLIT*CPS)     // 1184 candidates per query at merge
#define RCAP  64               // refine-list capacity
#define MARGIN 4.25f           // approx err (~1.5) *2 + quantization slack
#define BIGF  3.0e38f

// -------- device scratch --------
__device__ unsigned g_mem_hi[NM * 128];   // bf16x2: col pair per u32
__device__ unsigned g_mem_lo[NM * 128];
__device__ unsigned g_q_hi[BQ * 128];
__device__ unsigned g_q_lo[BQ * 128];
__device__ float    g_mem_sq[NM];
__device__ float    g_q_sq[BQ];
__device__ uint32_t g_cand[BQ * NC2];     // packed: arg-bits[31:11] | m_rel[10:0]
__device__ float    g_h_mem[NM * 256];    // tanh(xW+b) fp32
__device__ float    g_h_q[BQ * 256];

// ===================== PTX helpers =====================
__device__ __forceinline__ uint32_t smem_u32(const void* p) {
    uint32_t a;
    asm("{ .reg .u64 t; cvta.to.shared.u64 t, %1; cvt.u32.u64 %0, t; }" : "=r"(a) : "l"(p));
    return a;
}
#define LDSM_X4(r0, r1, r2, r3, addr) \
    asm volatile("ldmatrix.sync.aligned.m8n8.x4.shared.b16 {%0,%1,%2,%3}, [%4];" \
        : "=r"(r0), "=r"(r1), "=r"(r2), "=r"(r3) : "r"(addr))

__device__ __forceinline__ void mma_bf16(float* c, const uint32_t* a,
                                         uint32_t b0, uint32_t b1) {
    asm volatile("mma.sync.aligned.m16n8k16.row.col.f32.bf16.bf16.f32 "
        "{%0,%1,%2,%3},{%4,%5,%6,%7},{%8,%9},{%0,%1,%2,%3};"
        : "+f"(c[0]), "+f"(c[1]), "+f"(c[2]), "+f"(c[3])
        : "r"(a[0]), "r"(a[1]), "r"(a[2]), "r"(a[3]), "r"(b0), "r"(b1));
}
__device__ __forceinline__ void mma_tf32(float* c,
                                         uint32_t a0, uint32_t a1, uint32_t a2, uint32_t a3,
                                         uint32_t b0, uint32_t b1) {
    asm volatile("mma.sync.aligned.m16n8k8.row.col.f32.tf32.tf32.f32 "
        "{%0,%1,%2,%3},{%4,%5,%6,%7},{%8,%9},{%0,%1,%2,%3};"
        : "+f"(c[0]), "+f"(c[1]), "+f"(c[2]), "+f"(c[3])
        : "r"(a0), "r"(a1), "r"(a2), "r"(a3), "r"(b0), "r"(b1));
}
__device__ __forceinline__ float tf32f(float x) {
    uint32_t u;
    asm("cvt.rna.tf32.f32 %0, %1;" : "=r"(u) : "f"(x));
    return __uint_as_float(u);
}

// bf16x2 unpack: even dim in low 16 bits, odd dim in high 16 bits
__device__ __forceinline__ float bflo(uint32_t v) { return __uint_as_float(v << 16); }
__device__ __forceinline__ float bfhi(uint32_t v) { return __uint_as_float(v & 0xffff0000u); }

// ============================================================
// Kernel 1a: tf32 4-TERM split GEMM + tanh: H = tanh(X@W + b).
// CTA 128 rows x 64 cols, 8 warps. In-kernel hi/lo conversion with the
// R5-proven k-permuted pair layout (ob = s*16 + half*2; hi at +e*4, lo +1).
// 4 terms (hh+hl+lh+ll) == exact product of split values -> fp32-class error.
// ============================================================
union GemmSmem {
    struct { float QS[128 * 36]; float WS[64 * 36]; } t;
    float HS[128 * 68];
};

__global__ __launch_bounds__(256, 2)
void gemm_tanh_kernel(const float* __restrict__ X, const float* __restrict__ W,
                      const float* __restrict__ bias,
                      float* __restrict__ H, int M)
{
    __shared__ __align__(16) GemmSmem gs;
    __shared__ float sbias[64];

    const int tid = threadIdx.x;
    const int lane = tid & 31;
    const int wid = tid >> 5;
    const int warp_q = wid & 3;
    const int warp_m = wid >> 2;
    const int g4 = lane >> 2;
    const int tg = lane & 3;

    const int q0 = blockIdx.x * 128;
    const int c0 = blockIdx.y * 64;

    if (tid < 64) sbias[tid] = bias[c0 + tid];

    float acc[2][4][4];
#pragma unroll
    for (int i = 0; i < 2; i++)
#pragma unroll
        for (int j = 0; j < 4; j++)
#pragma unroll
            for (int c = 0; c < 4; c++) acc[i][j][c] = 0.f;

    for (int kc = 0; kc < DD; kc += 16) {
        // ---- QS fill: 128 rows x 16 k, in-kernel tf32 hi/lo split ----
#pragma unroll
        for (int it = 0; it < 2; it++) {
            int idx = tid + 256 * it;            // 512 float4
            int q = idx >> 2;
            int k4 = (idx & 3) * 4;
            float4 v = make_float4(0.f, 0.f, 0.f, 0.f);
            if (q0 + q < M)
                v = *(const float4*)&X[(size_t)(q0 + q) * DD + kc + k4];
            int s = k4 >> 3, half = (k4 >> 2) & 1;
            int ob = s * 16 + half * 2;
            float vv[4] = {v.x, v.y, v.z, v.w};
#pragma unroll
            for (int e = 0; e < 4; e++) {
                float hi = tf32f(vv[e]);
                float lo = tf32f(vv[e] - hi);
                gs.t.QS[q * 36 + ob + e * 4 + 0] = hi;
                gs.t.QS[q * 36 + ob + e * 4 + 1] = lo;
            }
        }
        // ---- WS fill: 64 cols x 16 k (W read column-wise), same layout ----
        {
            int r = tid >> 2;                    // column within block (0..63)
            int k4 = (tid & 3) * 4;
            int s = k4 >> 3, half = (k4 >> 2) & 1;
            int ob = s * 16 + half * 2;
#pragma unroll
            for (int e = 0; e < 4; e++) {
                float w = W[(size_t)(kc + k4 + e) * DD + c0 + r];
                float hi = tf32f(w);
                float lo = tf32f(w - hi);
                gs.t.WS[r * 36 + ob + e * 4 + 0] = hi;
                gs.t.WS[r * 36 + ob + e * 4 + 1] = lo;
            }
        }
        __syncthreads();

#pragma unroll
        for (int s = 0; s < 2; s++) {
            const int off = s * 16 + tg * 4;
            uint32_t ah[2][4], al[2][4];
#pragma unroll
            for (int i = 0; i < 2; i++) {
                int qr = warp_q * 32 + i * 16 + g4;
                float4 p0 = *(const float4*)&gs.t.QS[qr * 36 + off];
                float4 p1 = *(const float4*)&gs.t.QS[(qr + 8) * 36 + off];
                ah[i][0] = __float_as_uint(p0.x); al[i][0] = __float_as_uint(p0.y);
                ah[i][2] = __float_as_uint(p0.z); al[i][2] = __float_as_uint(p0.w);
                ah[i][1] = __float_as_uint(p1.x); al[i][1] = __float_as_uint(p1.y);
                ah[i][3] = __float_as_uint(p1.z); al[i][3] = __float_as_uint(p1.w);
            }
            uint32_t bh[4][2], bl[4][2];
#pragma unroll
            for (int j = 0; j < 4; j++) {
                int mr = warp_m * 32 + j * 8 + g4;
                float4 p = *(const float4*)&gs.t.WS[mr * 36 + off];
                bh[j][0] = __float_as_uint(p.x); bl[j][0] = __float_as_uint(p.y);
                bh[j][1] = __float_as_uint(p.z); bl[j][1] = __float_as_uint(p.w);
            }
#pragma unroll
            for (int i = 0; i < 2; i++)
#pragma unroll
                for (int j = 0; j < 4; j++) {
                    mma_tf32(acc[i][j], ah[i][0], ah[i][1], ah[i][2], ah[i][3],
                             bh[j][0], bh[j][1]);
                    mma_tf32(acc[i][j], ah[i][0], ah[i][1], ah[i][2], ah[i][3],
                             bl[j][0], bl[j][1]);
                    mma_tf32(acc[i][j], al[i][0], al[i][1], al[i][2], al[i][3],
                             bh[j][0], bh[j][1]);
                    mma_tf32(acc[i][j], al[i][0], al[i][1], al[i][2], al[i][3],
                             bl[j][0], bl[j][1]);
                }
        }
        __syncthreads();
    }

    // epilogue: bias + tanh -> smem stage -> coalesced global write
#pragma unroll
    for (int i = 0; i < 2; i++)
#pragma unroll
        for (int r = 0; r < 2; r++) {
            int q = warp_q * 32 + i * 16 + r * 8 + g4;
#pragma unroll
            for (int j = 0; j < 4; j++) {
                int ml = warp_m * 32 + j * 8 + 2 * tg;
                float vA = tanhf(acc[i][j][r * 2 + 0] + sbias[ml]);
                float vB = tanhf(acc[i][j][r * 2 + 1] + sbias[ml + 1]);
                *(float2*)&gs.HS[q * 68 + ml] = make_float2(vA, vB);
            }
        }
    __syncthreads();

#pragma unroll
    for (int it = 0; it < 8; it++) {
        int idx = tid + 256 * it;
        int row = idx >> 4, f4 = idx & 15;
        if (q0 + row < M)
            *(float4*)&H[(size_t)(q0 + row) * DD + c0 + f4 * 4] =
                *(const float4*)&gs.HS[row * 68 + f4 * 4];
    }
}

// ============================================================
// Kernel 1b: Norm/rescale/split: one warp per row. Reads fp32 H, writes
// bf16 hi/lo packed + SQ. scale = (norm>0.95) ? 0.95/norm : 1.
// FIX vs R12/R13: output row stride is 128 u32 (was 64 -> rows overlapped).
// ============================================================
__global__ void norm_split_kernel(const float* __restrict__ H,
                                  unsigned* __restrict__ Hhi, unsigned* __restrict__ Hlo,
                                  float* __restrict__ SQ, int M)
{
    const int lane = threadIdx.x & 31;
    const int wid = threadIdx.x >> 5;
    const int row = blockIdx.x * 8 + wid;
    if (row >= M) return;

    float4 a = *(const float4*)&H[(size_t)row * 256 + lane * 8];
    float4 b = *(const float4*)&H[(size_t)row * 256 + lane * 8 + 4];
    float ss = a.x * a.x + a.y * a.y + a.z * a.z + a.w * a.w
             + b.x * b.x + b.y * b.y + b.z * b.z + b.w * b.w;
#pragma unroll
    for (int off = 16; off; off >>= 1)
        ss += __shfl_xor_sync(0xffffffffu, ss, off);

    float norm = sqrtf(ss);
    float sc = (norm > 0.95f) ? 0.95f / norm : 1.0f;
    if (lane == 0) SQ[row] = ss * sc * sc;

    float v[8] = {a.x * sc, a.y * sc, a.z * sc, a.w * sc,
                  b.x * sc, b.y * sc, b.z * sc, b.w * sc};
    uint32_t hiw[4], low[4];
#pragma unroll
    for (int p = 0; p < 4; p++) {
        float vx = v[2 * p], vy = v[2 * p + 1];
        __nv_bfloat16 hx = __float2bfloat16(vx);
        __nv_bfloat16 hy = __float2bfloat16(vy);
        __nv_bfloat16 lx = __float2bfloat16(vx - __bfloat162float(hx));
        __nv_bfloat16 ly = __float2bfloat16(vy - __bfloat162float(hy));
        hiw[p] = ((unsigned)__bfloat16_as_ushort(hy) << 16) | __bfloat16_as_ushort(hx);
        low[p] = ((unsigned)__bfloat16_as_ushort(ly) << 16) | __bfloat16_as_ushort(lx);
    }
    *(uint4*)&Hhi[(size_t)row * 128 + lane * 4] = make_uint4(hiw[0], hiw[1], hiw[2], hiw[3]);
    *(uint4*)&Hlo[(size_t)row * 128 + lane * 4] = make_uint4(low[0], low[1], low[2], low[3]);
}

// ============================================================
// Kernel 2: bf16 hi-only mma pruning pass (UNCHANGED from R11 — passing).
// ============================================================
#define RS       144
#define QCH_B    (128 * RS)
#define MCH_B    (64 * RS)
#define OFF_Q    0
#define OFF_M    (4 * QCH_B)
#define OFF_YS   (OFF_M + 4 * MCH_B)
#define OFF_RY   (OFF_YS + 256)
#define DSMEM_SZ (OFF_RY + 256)

__device__ __forceinline__ void ins4u(uint32_t (&la)[4], uint32_t& worst, uint32_t pk) {
    int mp = 0; uint32_t mv = la[0];
    if (la[1] > mv) { mv = la[1]; mp = 1; }
    if (la[2] > mv) { mv = la[2]; mp = 2; }
    if (la[3] > mv) { mv = la[3]; mp = 3; }
    la[mp] = pk;
    mv = la[0];
    if (la[1] > mv) mv = la[1];
    if (la[2] > mv) mv = la[2];
    if (la[3] > mv) mv = la[3];
    worst = mv;
}

__global__ __launch_bounds__(256, 2)
void dist_topk_kernel()
{
    extern __shared__ char sb[];
    const uint32_t sbase = smem_u32(sb);
    float* tYS = (float*)(sb + OFF_YS);
    float* tRY = (float*)(sb + OFF_RY);

    const int tid = threadIdx.x;
    const int lane = tid & 31;
    const int wid = tid >> 5;
    const int warp_q = wid & 3;
    const int warp_m = wid >> 2;
    const int g4 = lane >> 2;
    const int tg = lane & 3;

    const int q0 = blockIdx.x * 128;
    const int mstart = blockIdx.y * SPLEN;
    const int mend = min(mstart + SPLEN, NM);

    const uint32_t aOff = (uint32_t)((warp_q * 32 + (lane & 7) + ((lane >> 3) & 1) * 8) * RS
                                     + (((lane >> 4) & 1) * 8) * 2);
    const uint32_t bOff = (uint32_t)((warp_m * 32 + (lane & 7) + ((lane >> 4) & 1) * 8) * RS
                                     + (((lane >> 3) & 1) * 8) * 2);
    const uint32_t u_q = sbase + OFF_Q;
    const uint32_t u_m = sbase + OFF_M;

    float xs[2][2], cA[2][2];
#pragma unroll
    for (int i = 0; i < 2; i++)
#pragma unroll
        for (int r = 0; r < 2; r++) {
            float v = g_q_sq[q0 + warp_q * 32 + i * 16 + r * 8 + g4];
            xs[i][r] = v;
            cA[i][r] = 2.0f / (1.0f - v);
        }

    uint32_t la[2][2][4];
    uint32_t lw[2][2];
#pragma unroll
    for (int i = 0; i < 2; i++)
#pragma unroll
        for (int r = 0; r < 2; r++) {
            lw[i][r] = 0xFFFFFFFFu;
#pragma unroll
            for (int l = 0; l < 4; l++) la[i][r][l] = 0xFFFFFFFFu;
        }

    {
        const uint4* pQH = (const uint4*)g_q_hi;
#pragma unroll
        for (int it = 0; it < 16; it++) {
            int idx = tid + 256 * it;
            int r = idx >> 5, u = idx & 31;
            int chunk = u >> 3, kb = u & 7;
            uint4 v = pQH[(size_t)(q0 + r) * 32 + u];
            *(uint4*)(sb + OFF_Q + chunk * QCH_B + r * RS + kb * 16) = v;
        }
    }

    const uint4* pMH = (const uint4*)g_mem_hi;

    for (int m0 = mstart; m0 < mend; m0 += 64) {
        __syncthreads();

        if (tid < 64) {
            int m = m0 + tid;
            float ys = (m < mend) ? g_mem_sq[m] : 0.f;
            tYS[tid] = ys;
            tRY[tid] = __frcp_rn(1.0f - ys);
        }
#pragma unroll
        for (int it = 0; it < 8; it++) {
            int idx = tid + 256 * it;
            int r = idx >> 5, u = idx & 31;
            int chunk = u >> 3, kb = u & 7;
            uint4 v = make_uint4(0u, 0u, 0u, 0u);
            if (m0 + r < mend) v = pMH[(size_t)(m0 + r) * 32 + u];
            *(uint4*)(sb + OFF_M + chunk * MCH_B + r * RS + kb * 16) = v;
        }
        __syncthreads();

        float acc[2][4][4];
#pragma unroll
        for (int i = 0; i < 2; i++)
#pragma unroll
            for (int j = 0; j < 4; j++)
#pragma unroll
                for (int c = 0; c < 4; c++) acc[i][j][c] = 0.f;

#pragma unroll
        for (int c = 0; c < 4; c++) {
            const uint32_t aBase = u_q + c * QCH_B + aOff;
            const uint32_t bBase = u_m + c * MCH_B + bOff;
#pragma unroll
            for (int ks = 0; ks < 4; ks++) {
                uint32_t ah[2][4], bh[2][4];
#pragma unroll
                for (int i = 0; i < 2; i++)
                    LDSM_X4(ah[i][0], ah[i][1], ah[i][2], ah[i][3],
                            aBase + ks * 32 + i * (16 * RS));
#pragma unroll
                for (int jj = 0; jj < 2; jj++)
                    LDSM_X4(bh[jj][0], bh[jj][1], bh[jj][2], bh[jj][3],
                            bBase + ks * 32 + jj * (16 * RS));
#pragma unroll
                for (int i = 0; i < 2; i++)
#pragma unroll
                    for (int j = 0; j < 4; j++) {
                        int jj = j >> 1, s = (j & 1) * 2;
                        mma_bf16(acc[i][j], ah[i], bh[jj][s], bh[jj][s + 1]);
                    }
            }
        }

        const int m0rel = m0 - mstart;
#pragma unroll
        for (int i = 0; i < 2; i++)
#pragma unroll
            for (int r = 0; r < 2; r++) {
                float xsi = xs[i][r], cc = cA[i][r];
#pragma unroll
                for (int j = 0; j < 4; j++) {
                    int ml = warp_m * 32 + j * 8 + 2 * tg;
                    int mA = m0 + ml;
                    float dA = acc[i][j][r * 2 + 0];
                    float dB = acc[i][j][r * 2 + 1];
                    float d2A = fmaxf(fmaf(-2.f, dA, xsi + tYS[ml]), 0.f);
                    float d2B = fmaxf(fmaf(-2.f, dB, xsi + tYS[ml + 1]), 0.f);
                    float tA = d2A * cc * tRY[ml];
                    float tB = d2B * cc * tRY[ml + 1];
                    uint32_t pkA = (__float_as_uint(tA) & 0xFFFFF800u)
                                   | (uint32_t)(m0rel + ml);
                    uint32_t pkB = (__float_as_uint(tB) & 0xFFFFF800u)
                                   | (uint32_t)(m0rel + ml + 1);
                    if (mA < mend && pkA < lw[i][r]) ins4u(la[i][r], lw[i][r], pkA);
                    if (mA + 1 < mend && pkB < lw[i][r]) ins4u(la[i][r], lw[i][r], pkB);
                }
            }
    }

#pragma unroll
    for (int i = 0; i < 2; i++)
#pragma unroll
        for (int r = 0; r < 2; r++) {
            int q = q0 + warp_q * 32 + i * 16 + r * 8 + g4;
            int base = (q * NSPLIT + blockIdx.y) * CPS + (warp_m * 4 + tg) * 4;
#pragma unroll
            for (int l = 0; l < 4; l++)
                g_cand[base + l] = la[i][r][l];
        }
}

// ============================================================
// Kernel 3: per-warp top-8 (u32) -> warp-parallel union 8th -> threshold ->
// refine list -> EXACT fp32 rerank -> softmax -> gather.
// ============================================================
__device__ __forceinline__ float dec_t(uint32_t v) {
    return __uint_as_float(v & 0xFFFFF800u);
}

__global__ void merge_kernel(const float* __restrict__ masks, float* __restrict__ out)
{
    __shared__ uint32_t cv[NC2];
    __shared__ uint32_t w8[8][8];
    __shared__ float qf[DD];
    __shared__ int   ridx[RCAP];
    __shared__ float ra[RCAP];
    __shared__ float sel_a[KSEL];
    __shared__ int   sel_i[KSEL];
    __shared__ float s_thresh;
    __shared__ int   scnt;

    const int q = blockIdx.x;
    const int tid = threadIdx.x;
    const int lane = tid & 31, wid = tid >> 5;

    if (tid == 0) scnt = 0;
    for (int c = tid; c < NC2; c += 256) cv[c] = g_cand[q * NC2 + c];
    if (tid < 128) {
        unsigned h = g_q_hi[q * 128 + tid];
        unsigned l = g_q_lo[q * 128 + tid];
        qf[2 * tid + 0] = bflo(h) + bflo(l);
        qf[2 * tid + 1] = bfhi(h) + bfhi(l);
    }
    __syncthreads();

    // ---- per-warp top-8 over its 148 candidates ----
    {
        const int wbase = wid * 148;
        uint32_t v[5];
#pragma unroll
        for (int k = 0; k < 5; k++) {
            int c = wbase + lane + 32 * k;
            v[k] = (lane + 32 * k < 148) ? cv[c] : 0xFFFFFFFFu;
        }
#pragma unroll
        for (int r = 0; r < 8; r++) {
            uint32_t lmin = v[0]; int pos = 0;
#pragma unroll
            for (int k = 1; k < 5; k++)
                if (v[k] < lmin) { lmin = v[k]; pos = k; }
            uint32_t rmin = lmin;
#pragma unroll
            for (int off = 16; off; off >>= 1)
                rmin = min(rmin, __shfl_xor_sync(0xffffffffu, rmin, off));
            unsigned ball = __ballot_sync(0xffffffffu, lmin == rmin);
            if (lane == (int)(__ffs(ball) - 1)) v[pos] = 0xFFFFFFFFu;
            if (lane == 0) w8[wid][r] = rmin;
        }
    }
    __syncthreads();

    // ---- warp-parallel 8th smallest of the 64-entry union ----
    if (wid == 0) {
        uint32_t v0 = ((uint32_t*)w8)[lane];
        uint32_t v1 = ((uint32_t*)w8)[lane + 32];
        uint32_t e8 = 0;
#pragma unroll
        for (int r = 0; r < 8; r++) {
            uint32_t lm = min(v0, v1);
            uint32_t rm = lm;
#pragma unroll
            for (int off = 16; off; off >>= 1)
                rm = min(rm, __shfl_xor_sync(0xffffffffu, rm, off));
            e8 = rm;
            unsigned ball = __ballot_sync(0xffffffffu, lm == rm);
            if (lane == (int)(__ffs(ball) - 1)) {
                if (v0 == rm) v0 = 0xFFFFFFFFu; else v1 = 0xFFFFFFFFu;
            }
        }
        if (lane == 0) s_thresh = 1.0f + dec_t(e8) + MARGIN;
    }
    __syncthreads();

    // ---- refine list ----
    const float thresh = s_thresh;
    for (int c = tid; c < NC2; c += 256) {
        uint32_t pv = cv[c];
        float t = dec_t(pv);
        if (1.0f + t <= thresh) {
            int idx = (c >> 5) * SPLEN + (int)(pv & 0x7FFu);
            if (idx < NM) {
                int p = atomicAdd(&scnt, 1);
                if (p < RCAP) ridx[p] = idx;
            }
        }
    }
    __syncthreads();
    const int cnt = min(scnt, RCAP);
    const float x_sq = g_q_sq[q];
    const float invx = 1.0f - x_sq;

    // ---- exact fp32 dots (warp per candidate) ----
    for (int c = wid; c < cnt; c += 8) {
        int m = ridx[c];
        const uint4* ph = (const uint4*)(g_mem_hi + (size_t)m * 128);
        const uint4* pl = (const uint4*)(g_mem_lo + (size_t)m * 128);
        uint4 h = ph[lane], l = pl[lane];
        const float* qp = &qf[lane * 8];
        float dot;
        dot  = (bflo(h.x) + bflo(l.x)) * qp[0];
        dot += (bfhi(h.x) + bfhi(l.x)) * qp[1];
        dot += (bflo(h.y) + bflo(l.y)) * qp[2];
        dot += (bfhi(h.y) + bfhi(l.y)) * qp[3];
        dot += (bflo(h.z) + bflo(l.z)) * qp[4];
        dot += (bfhi(h.z) + bfhi(l.z)) * qp[5];
        dot += (bflo(h.w) + bflo(l.w)) * qp[6];
        dot += (bfhi(h.w) + bfhi(l.w)) * qp[7];
#pragma unroll
        for (int off = 16; off; off >>= 1)
            dot += __shfl_xor_sync(0xffffffffu, dot, off);
        if (lane == 0) {
            float ysq = g_mem_sq[m];
            float d2 = fmaxf(x_sq + ysq - 2.f * dot, 0.f);
            float arg = 1.f + 2.f * d2 / (invx * (1.f - ysq) + 1e-8f);
            ra[c] = fmaxf(arg, 1.0f + 1e-6f);
        }
    }
    __syncthreads();

    // ---- final exact top-8 (warp 0), lexicographic (arg, idx) ----
    if (wid == 0) {
        for (int r = 0; r < KSEL; r++) {
            float ba = BIGF; int bi = 0x7fffffff, bp = 0;
            for (int c = lane; c < cnt; c += 32) {
                float a = ra[c]; int i = ridx[c];
                if (a < ba || (a == ba && i < bi)) { ba = a; bi = i; bp = c; }
            }
#pragma unroll
            for (int off = 16; off; off >>= 1) {
                float oa = __shfl_down_sync(0xffffffffu, ba, off);
                int oi = __shfl_down_sync(0xffffffffu, bi, off);
                int op = __shfl_down_sync(0xffffffffu, bp, off);
                if (oa < ba || (oa == ba && oi < bi)) { ba = oa; bi = oi; bp = op; }
            }
            ba = __shfl_sync(0xffffffffu, ba, 0);
            bi = __shfl_sync(0xffffffffu, bi, 0);
            bp = __shfl_sync(0xffffffffu, bp, 0);
            if (lane == 0) {
                sel_a[r] = ba; sel_i[r] = bi;
                ra[bp] = BIGF;
            }
            __syncwarp();
        }
    }
    __syncthreads();

    if (tid == 0) {
        float d[KSEL];
#pragma unroll
        for (int s = 0; s < KSEL; s++) d[s] = acoshf(sel_a[s]);
        float d0 = d[0];
        float e[KSEL], sum = 0.f;
#pragma unroll
        for (int s = 0; s < KSEL; s++) { e[s] = expf(d0 - d[s]); sum += e[s]; }
        float inv = 1.0f / sum;
#pragma unroll
        for (int s = 0; s < KSEL; s++) out[q * KSEL + s] = e[s] * inv;
    }
    __syncthreads();

    float4* hout = (float4*)(out + (size_t)BQ * KSEL);
    for (int e = tid; e < KSEL * (MAXA / 4); e += 256) {
        int s = e / (MAXA / 4), a4 = e - s * (MAXA / 4);
        const float4* src = (const float4*)(masks + (size_t)sel_i[s] * MAXA);
        hout[((size_t)q * KSEL + s) * (MAXA / 4) + a4] = src[a4];
    }
}

// ============================================================
extern "C" void kernel_launch(void* const* d_in, const int* in_sizes, int n_in,
                              void* d_out, int out_size)
{
    (void)in_sizes; (void)n_in; (void)out_size;
    const float* q_emb  = (const float*)d_in[0];
    const float* m_emb  = (const float*)d_in[1];
    const float* masks  = (const float*)d_in[2];
    const float* W      = (const float*)d_in[3];
    const float* bias   = (const float*)d_in[4];
    float* out = (float*)d_out;

    unsigned *d_mhi, *d_mlo, *d_qhi, *d_qlo;
    float *d_msq, *d_qsq, *d_hm, *d_hq;
    cudaGetSymbolAddress((void**)&d_mhi, g_mem_hi);
    cudaGetSymbolAddress((void**)&d_mlo, g_mem_lo);
    cudaGetSymbolAddress((void**)&d_qhi, g_q_hi);
    cudaGetSymbolAddress((void**)&d_qlo, g_q_lo);
    cudaGetSymbolAddress((void**)&d_msq, g_mem_sq);
    cudaGetSymbolAddress((void**)&d_qsq, g_q_sq);
    cudaGetSymbolAddress((void**)&d_hm,  g_h_mem);
    cudaGetSymbolAddress((void**)&d_hq,  g_h_q);

    cudaFuncSetAttribute(dist_topk_kernel,
                         cudaFuncAttributeMaxDynamicSharedMemorySize, DSMEM_SZ);

    // tf32 4-term GEMM + tanh (in-kernel split)
    dim3 gm((NM + 127) / 128, 4), gq((BQ + 127) / 128, 4);
    gemm_tanh_kernel<<<gm, 256>>>(m_emb, W, bias, d_hm, NM);
    gemm_tanh_kernel<<<gq, 256>>>(q_emb, W, bias, d_hq, BQ);

    // Poincare rescale + |h|^2 + bf16 hi/lo split
    norm_split_kernel<<<(NM + 7) / 8, 256>>>(d_hm, d_mhi, d_mlo, d_msq, NM);
    norm_split_kernel<<<(BQ + 7) / 8, 256>>>(d_hq, d_qhi, d_qlo, d_qsq, BQ);

    dim3 g2(BQ / 128, NSPLIT);
    dist_topk_kernel<<<g2, 256, DSMEM_SZ>>>();

    merge_kernel<<<BQ, 256>>>(masks, out);
}